// round 4
// baseline (speedup 1.0000x reference)
#include <cuda_runtime.h>
#include <cuda_bf16.h>
#include <math.h>
#include <stdint.h>

#define NN 4096
#define EE 65536

// ------------------- scratch (static device globals; no allocs) -------------
__device__ float g_P[NN * 512];
__device__ float g_A[NN * 256];
__device__ float g_B[NN * 256];
__device__ float g_C[NN * 256];
__device__ float g_D[NN * 128];
__device__ float g_E[NN * 128];
__device__ int   g_cnt[NN];
__device__ float g_dinv[NN];
// tf32 pre-rounded operands
__device__ float g_Xt[NN * NN];      // x rounded (64MB)
__device__ float g_Wt[NN * 512];     // [Wl|Wr] rounded, interleaved rows
__device__ float g_Ht[NN * 128];     // h5 rounded
__device__ float g_OWt[128 * 16384]; // out_W rounded

__device__ __forceinline__ uint32_t f2tf32(float f) {
    uint32_t r;
    asm("cvt.rna.tf32.f32 %0, %1;" : "=r"(r) : "f"(f));
    return r;
}

// ------------------------------- utility kernels ----------------------------
__global__ void k_zero_cnt() {
    int i = blockIdx.x * blockDim.x + threadIdx.x;
    if (i < NN) g_cnt[i] = 0;
}
__global__ void k_count(const int* __restrict__ dst) {
    int e = blockIdx.x * blockDim.x + threadIdx.x;
    if (e < EE) atomicAdd(&g_cnt[dst[e]], 1);
}
__global__ void k_dinv() {
    int i = blockIdx.x * blockDim.x + threadIdx.x;
    if (i < NN) g_dinv[i] = rsqrtf((float)(g_cnt[i] + 1));
}
__global__ void k_zero_f(float* __restrict__ p, int n) {
    int i = blockIdx.x * blockDim.x + threadIdx.x;
    if (i < n) p[i] = 0.0f;
}
// round n floats (n % 4 == 0) to tf32
__global__ void k_round(const float* __restrict__ in, float* __restrict__ out, int n4) {
    int i = blockIdx.x * blockDim.x + threadIdx.x;
    if (i >= n4) return;
    float4 v = ((const float4*)in)[i];
    v.x = __uint_as_float(f2tf32(v.x));
    v.y = __uint_as_float(f2tf32(v.y));
    v.z = __uint_as_float(f2tf32(v.z));
    v.w = __uint_as_float(f2tf32(v.w));
    ((float4*)out)[i] = v;
}
// build g_Wt: row k = [Wl[k,:256] | Wr[k,:256]], rounded
__global__ void k_round_pair(const float* __restrict__ Wl, const float* __restrict__ Wr) {
    int i = blockIdx.x * blockDim.x + threadIdx.x;   // over NN*512/4 float4s
    if (i >= NN * 128) return;
    int k = i >> 7;          // row
    int q = i & 127;         // float4 within row (512 floats = 128 f4)
    const float* srcp = (q < 64) ? (Wl + (size_t)k * 256 + q * 4)
                                 : (Wr + (size_t)k * 256 + (q - 64) * 4);
    float4 v = *(const float4*)srcp;
    v.x = __uint_as_float(f2tf32(v.x));
    v.y = __uint_as_float(f2tf32(v.y));
    v.z = __uint_as_float(f2tf32(v.z));
    v.w = __uint_as_float(f2tf32(v.w));
    ((float4*)g_Wt)[i] = v;
}
__global__ void k_sage_agg(const int* __restrict__ src, const int* __restrict__ dst) {
    int t = blockIdx.x * blockDim.x + threadIdx.x;
    if (t >= EE * 64) return;
    int e = t >> 6;
    int q = t & 63;
    int s = src[e];
    int d = dst[e];
    float4 v = ((const float4*)(g_P + (size_t)s * 512))[q];
    float* out = g_A + (size_t)d * 256 + q * 4;
    atomicAdd(out + 0, v.x);
    atomicAdd(out + 1, v.y);
    atomicAdd(out + 2, v.z);
    atomicAdd(out + 3, v.w);
}
__global__ void k_sage_combine(const float* __restrict__ bl) {
    int i = blockIdx.x * blockDim.x + threadIdx.x;
    if (i >= NN * 256) return;
    int v = i >> 8;
    int c = i & 255;
    float inv = 1.0f / fmaxf((float)g_cnt[v], 1.0f);
    float val = g_A[i] * inv + bl[c] + g_P[(size_t)v * 512 + 256 + c];
    g_B[i] = fmaxf(val, 0.0f);
}
__global__ void k_gcn_init(const float* __restrict__ hw, float* __restrict__ agg, int H) {
    int i = blockIdx.x * blockDim.x + threadIdx.x;
    if (i >= NN * H) return;
    int v = i / H;
    float dv = g_dinv[v];
    agg[i] = dv * dv * hw[i];
}
__global__ void k_gcn_agg(const int* __restrict__ src, const int* __restrict__ dst,
                          const float* __restrict__ hw, float* __restrict__ agg, int Hq) {
    int t = blockIdx.x * blockDim.x + threadIdx.x;
    if (t >= EE * Hq) return;
    int e = t / Hq;
    int q = t - e * Hq;
    int s = src[e];
    int d = dst[e];
    float norm = g_dinv[s] * g_dinv[d];
    int H = Hq * 4;
    float4 v = ((const float4*)(hw + (size_t)s * H))[q];
    float* out = agg + (size_t)d * H + q * 4;
    atomicAdd(out + 0, norm * v.x);
    atomicAdd(out + 1, norm * v.y);
    atomicAdd(out + 2, norm * v.z);
    atomicAdd(out + 3, norm * v.w);
}
__global__ void k_bias_relu(const float* __restrict__ in, const float* __restrict__ b,
                            float* __restrict__ out, int H) {
    int i = blockIdx.x * blockDim.x + threadIdx.x;
    if (i >= NN * H) return;
    int c = i % H;
    out[i] = fmaxf(in[i] + b[c], 0.0f);
}

// ---------------------------- fp32 SIMT GEMM (small layers) -----------------
__global__ void __launch_bounds__(256, 2)
sgemm(int M, int N, int K,
      const float* __restrict__ A, int lda,
      const float* __restrict__ B, int ldb,
      const float* __restrict__ B2, int nsplit,
      float* __restrict__ C, int ldc,
      const float* __restrict__ bias, int do_relu)
{
    const int BK = 8;
    __shared__ float As[2][BK][128];
    __shared__ float Bs[2][BK][128];

    int tid = threadIdx.x;
    int tx = tid & 15;
    int ty = tid >> 4;
    int row0 = blockIdx.y * 128;
    int col0 = blockIdx.x * 128;

    const float* Bp = B;
    int cb = col0;
    if (col0 >= nsplit) { Bp = B2; cb = col0 - nsplit; }

    int am = tid >> 1;
    int ak = (tid & 1) << 2;
    int bk = tid >> 5;
    int bn = (tid & 31) << 2;

    const float* Aptr = A + (size_t)(row0 + am) * lda + ak;
    const float* Bptr = Bp + (size_t)bk * ldb + cb + bn;
    size_t bstep = (size_t)BK * ldb;

    float4 av = *(const float4*)Aptr;
    float4 bv = *(const float4*)Bptr;
    As[0][ak + 0][am] = av.x;
    As[0][ak + 1][am] = av.y;
    As[0][ak + 2][am] = av.z;
    As[0][ak + 3][am] = av.w;
    *(float4*)&Bs[0][bk][bn] = bv;
    __syncthreads();

    float acc[8][8];
    #pragma unroll
    for (int i = 0; i < 8; i++)
        #pragma unroll
        for (int j = 0; j < 8; j++) acc[i][j] = 0.0f;

    int ntiles = K / BK;
    for (int t = 0; t < ntiles; t++) {
        int buf = t & 1;
        if (t + 1 < ntiles) {
            av = *(const float4*)(Aptr + (size_t)(t + 1) * BK);
            bv = *(const float4*)(Bptr + (size_t)(t + 1) * bstep);
        }
        #pragma unroll
        for (int k = 0; k < BK; k++) {
            float a[8], b[8];
            *(float4*)&a[0] = *(float4*)&As[buf][k][ty * 8];
            *(float4*)&a[4] = *(float4*)&As[buf][k][ty * 8 + 4];
            *(float4*)&b[0] = *(float4*)&Bs[buf][k][tx * 8];
            *(float4*)&b[4] = *(float4*)&Bs[buf][k][tx * 8 + 4];
            #pragma unroll
            for (int i = 0; i < 8; i++)
                #pragma unroll
                for (int j = 0; j < 8; j++)
                    acc[i][j] = fmaf(a[i], b[j], acc[i][j]);
        }
        if (t + 1 < ntiles) {
            int nb = buf ^ 1;
            As[nb][ak + 0][am] = av.x;
            As[nb][ak + 1][am] = av.y;
            As[nb][ak + 2][am] = av.z;
            As[nb][ak + 3][am] = av.w;
            *(float4*)&Bs[nb][bk][bn] = bv;
            __syncthreads();
        }
    }

    #pragma unroll
    for (int i = 0; i < 8; i++) {
        int gm = row0 + ty * 8 + i;
        #pragma unroll
        for (int j = 0; j < 8; j += 4) {
            int gn = col0 + tx * 8 + j;
            float4 v;
            v.x = acc[i][j + 0];
            v.y = acc[i][j + 1];
            v.z = acc[i][j + 2];
            v.w = acc[i][j + 3];
            if (bias) {
                v.x += bias[gn + 0];
                v.y += bias[gn + 1];
                v.z += bias[gn + 2];
                v.w += bias[gn + 3];
            }
            if (do_relu) {
                v.x = fmaxf(v.x, 0.0f);
                v.y = fmaxf(v.y, 0.0f);
                v.z = fmaxf(v.z, 0.0f);
                v.w = fmaxf(v.w, 0.0f);
            }
            *(float4*)&C[(size_t)gm * ldc + gn] = v;
        }
    }
}

// ------------------- tf32 tensor-core GEMM, fragment-major smem -------------
// Inputs MUST be pre-rounded to tf32 (values representable in tf32).
// BM=128, BK=16, 256 threads. Smem tiles are stored in mma fragment order:
//  A frag (m16k8): reg = (k%8>=4 ? 2:0)+(m%16>=8 ? 1:0), lane = (m%8)*4 + k%4
//  B frag (k8n8):  reg = (k%8>=4),                      lane = (n%8)*4 + k%4
// so the consumer loads one float4 (A) / one float2 (B) per fragment.

__device__ __forceinline__ void mma_tf32(float* c, const uint32_t* a, const uint32_t* b) {
    asm volatile(
        "mma.sync.aligned.m16n8k8.row.col.f32.tf32.tf32.f32 "
        "{%0,%1,%2,%3}, {%4,%5,%6,%7}, {%8,%9}, {%0,%1,%2,%3};"
        : "+f"(c[0]), "+f"(c[1]), "+f"(c[2]), "+f"(c[3])
        : "r"(a[0]), "r"(a[1]), "r"(a[2]), "r"(a[3]), "r"(b[0]), "r"(b[1]));
}

template<int BN, int WM, int WN>
__global__ void __launch_bounds__(256, 2)
gemm_tf32f(int M, int N, int K,
           const float* __restrict__ A, int lda,
           const float* __restrict__ B, int ldb,
           float* __restrict__ C, int ldc,
           const float* __restrict__ bias)
{
    const int BK = 16;
    const int MFRAG = WM / 16;
    const int NFRAG = WN / 8;
    const int WARPS_N = BN / WN;
    const int NB4 = (BK * BN / 4) / 256;   // B float4 loads per thread

    __shared__ float AsF[2][2048];         // 2 k-slices * 8 m-tiles * 32 lanes * 4 regs
    __shared__ float BsF[2][BK * BN];      // 2 k-slices * (BN/8) n-tiles * 32 lanes * 2 regs

    int tid = threadIdx.x;
    int lane = tid & 31;
    int warp = tid >> 5;
    int warp_m = warp / WARPS_N;
    int warp_n = warp % WARPS_N;

    int row0 = blockIdx.y * 128;
    int col0 = blockIdx.x * BN;

    // A loader: 2 float4 per thread
    int ar[2], akc[2];
    #pragma unroll
    for (int l = 0; l < 2; l++) {
        int i = tid + l * 256;
        ar[l]  = i >> 2;
        akc[l] = (i & 3) << 2;
    }
    // B loader
    int bkk[2], bnn[2];
    #pragma unroll
    for (int l = 0; l < NB4; l++) {
        int i = tid + l * 256;
        bkk[l] = i / (BN / 4);
        bnn[l] = (i % (BN / 4)) * 4;
    }

    float4 avp[2], bvp[2];
    #pragma unroll
    for (int l = 0; l < 2; l++)
        avp[l] = *(const float4*)&A[(size_t)(row0 + ar[l]) * lda + akc[l]];
    #pragma unroll
    for (int l = 0; l < NB4; l++)
        bvp[l] = *(const float4*)&B[(size_t)bkk[l] * ldb + col0 + bnn[l]];

    // fragment-major store helpers
    auto storeA = [&](int buf) {
        #pragma unroll
        for (int l = 0; l < 2; l++) {
            float v[4] = {avp[l].x, avp[l].y, avp[l].z, avp[l].w};
            int t8 = ar[l] >> 4;          // m-tile
            int mr = ar[l] & 15;
            int lane_hi = (mr & 7) << 2;
            int regm = (mr >= 8) ? 1 : 0;
            #pragma unroll
            for (int j = 0; j < 4; j++) {
                int k = akc[l] + j;
                int s = k >> 3, kk = k & 7;
                int fl = lane_hi | (kk & 3);
                int reg = ((kk >= 4) ? 2 : 0) + regm;
                AsF[buf][((((s << 3) + t8) << 5) + fl) * 4 + reg] = v[j];
            }
        }
    };
    auto storeB = [&](int buf) {
        #pragma unroll
        for (int l = 0; l < NB4; l++) {
            float v[4] = {bvp[l].x, bvp[l].y, bvp[l].z, bvp[l].w};
            int k = bkk[l];
            int s = k >> 3, kk = k & 7;
            int kl = kk & 3;
            int regk = (kk >= 4) ? 1 : 0;
            #pragma unroll
            for (int j = 0; j < 4; j++) {
                int n = bnn[l] + j;
                int u = n >> 3, nc = n & 7;
                int fl = (nc << 2) | kl;
                BsF[buf][((s * (BN / 8) + u) * 32 + fl) * 2 + regk] = v[j];
            }
        }
    };

    storeA(0);
    storeB(0);
    __syncthreads();

    float acc[MFRAG][NFRAG][4];
    #pragma unroll
    for (int mi = 0; mi < MFRAG; mi++)
        #pragma unroll
        for (int ni = 0; ni < NFRAG; ni++)
            #pragma unroll
            for (int j = 0; j < 4; j++) acc[mi][ni][j] = 0.0f;

    int ntiles = K / BK;
    for (int t = 0; t < ntiles; t++) {
        int buf = t & 1;
        if (t + 1 < ntiles) {
            #pragma unroll
            for (int l = 0; l < 2; l++)
                avp[l] = *(const float4*)&A[(size_t)(row0 + ar[l]) * lda + (t + 1) * BK + akc[l]];
            #pragma unroll
            for (int l = 0; l < NB4; l++)
                bvp[l] = *(const float4*)&B[(size_t)((t + 1) * BK + bkk[l]) * ldb + col0 + bnn[l]];
        }

        #pragma unroll
        for (int s = 0; s < 2; s++) {
            uint32_t afr[MFRAG][4];
            uint32_t bfr[NFRAG][2];
            #pragma unroll
            for (int mi = 0; mi < MFRAG; mi++) {
                int t8 = warp_m * MFRAG + mi;
                float4 fa = *(const float4*)&AsF[buf][((((s << 3) + t8) << 5) + lane) * 4];
                afr[mi][0] = __float_as_uint(fa.x);
                afr[mi][1] = __float_as_uint(fa.y);
                afr[mi][2] = __float_as_uint(fa.z);
                afr[mi][3] = __float_as_uint(fa.w);
            }
            #pragma unroll
            for (int ni = 0; ni < NFRAG; ni++) {
                int u = warp_n * NFRAG + ni;
                float2 fb = *(const float2*)&BsF[buf][((s * (BN / 8) + u) * 32 + lane) * 2];
                bfr[ni][0] = __float_as_uint(fb.x);
                bfr[ni][1] = __float_as_uint(fb.y);
            }
            #pragma unroll
            for (int mi = 0; mi < MFRAG; mi++)
                #pragma unroll
                for (int ni = 0; ni < NFRAG; ni++)
                    mma_tf32(acc[mi][ni], afr[mi], bfr[ni]);
        }

        if (t + 1 < ntiles) {
            int nb = buf ^ 1;
            storeA(nb);
            storeB(nb);
            __syncthreads();
        }
    }

    int qm = lane >> 2;
    int qk = lane & 3;
    #pragma unroll
    for (int mi = 0; mi < MFRAG; mi++) {
        int r = row0 + warp_m * WM + mi * 16 + qm;
        #pragma unroll
        for (int ni = 0; ni < NFRAG; ni++) {
            int c = col0 + warp_n * WN + ni * 8 + 2 * qk;
            float2 v0 = make_float2(acc[mi][ni][0], acc[mi][ni][1]);
            float2 v1 = make_float2(acc[mi][ni][2], acc[mi][ni][3]);
            if (bias) {
                float2 bb = *(const float2*)&bias[c];
                v0.x += bb.x; v0.y += bb.y;
                v1.x += bb.x; v1.y += bb.y;
            }
            *(float2*)&C[(size_t)r * ldc + c] = v0;
            *(float2*)&C[(size_t)(r + 8) * ldc + c] = v1;
        }
    }
}

// ------------------------------ host orchestration ---------------------------
static void launch_gemm(int M, int N, int K,
                        const float* A, int lda,
                        const float* B, int ldb,
                        const float* B2, int nsplit,
                        float* C, int ldc,
                        const float* bias, int do_relu)
{
    dim3 grid(N / 128, M / 128);
    sgemm<<<grid, 256>>>(M, N, K, A, lda, B, ldb, B2, nsplit, C, ldc, bias, do_relu);
}

extern "C" void kernel_launch(void* const* d_in, const int* in_sizes, int n_in,
                              void* d_out, int out_size)
{
    const float* x       = (const float*)d_in[0];
    const int*   eidx    = (const int*)  d_in[1];
    const float* sage_Wl = (const float*)d_in[2];
    const float* sage_bl = (const float*)d_in[3];
    const float* sage_Wr = (const float*)d_in[4];
    const float* gcn1_W  = (const float*)d_in[5];
    const float* gcn1_b  = (const float*)d_in[6];
    const float* gcn2_W  = (const float*)d_in[7];
    const float* gcn2_b  = (const float*)d_in[8];
    const float* fc1_W   = (const float*)d_in[9];
    const float* fc1_b   = (const float*)d_in[10];
    const float* fc2_W   = (const float*)d_in[11];
    const float* fc2_b   = (const float*)d_in[12];
    const float* out_W   = (const float*)d_in[13];
    const float* out_b   = (const float*)d_in[14];
    float* out = (float*)d_out;

    const int* src = eidx;
    const int* dst = eidx + EE;

    float *P, *A, *B, *C, *D, *E, *Xt, *Wt, *Ht, *OWt;
    cudaGetSymbolAddress((void**)&P, g_P);
    cudaGetSymbolAddress((void**)&A, g_A);
    cudaGetSymbolAddress((void**)&B, g_B);
    cudaGetSymbolAddress((void**)&C, g_C);
    cudaGetSymbolAddress((void**)&D, g_D);
    cudaGetSymbolAddress((void**)&E, g_E);
    cudaGetSymbolAddress((void**)&Xt, g_Xt);
    cudaGetSymbolAddress((void**)&Wt, g_Wt);
    cudaGetSymbolAddress((void**)&Ht, g_Ht);
    cudaGetSymbolAddress((void**)&OWt, g_OWt);

    const int TPB = 256;

    k_zero_cnt<<<(NN + TPB - 1) / TPB, TPB>>>();
    k_count<<<(EE + TPB - 1) / TPB, TPB>>>(dst);
    k_dinv<<<(NN + TPB - 1) / TPB, TPB>>>();

    // pre-round operands of the two big GEMMs to tf32
    k_round<<<(NN * NN / 4 + TPB - 1) / TPB, TPB>>>(x, Xt, NN * NN / 4);
    k_round_pair<<<(NN * 128 + TPB - 1) / TPB, TPB>>>(sage_Wl, sage_Wr);
    k_round<<<(128 * 16384 / 4 + TPB - 1) / TPB, TPB>>>(out_W, OWt, 128 * 16384 / 4);

    // P = x @ [Wl | Wr]  (4096 x 512 x 4096) tf32 tensor cores
    {
        dim3 grid(512 / 64, NN / 128);
        gemm_tf32f<64, 32, 32><<<grid, 256>>>(NN, 512, NN, Xt, NN, Wt, 512, P, 512, nullptr);
    }

    // SAGE
    k_zero_f<<<(NN * 256 + TPB - 1) / TPB, TPB>>>(A, NN * 256);
    k_sage_agg<<<(EE * 64 + TPB - 1) / TPB, TPB>>>(src, dst);
    k_sage_combine<<<(NN * 256 + TPB - 1) / TPB, TPB>>>(sage_bl);

    // GCN1 (fp32 SIMT)
    launch_gemm(NN, 256, 256, B, 256, gcn1_W, 256, gcn1_W, 256, C, 256, nullptr, 0);
    k_gcn_init<<<(NN * 256 + TPB - 1) / TPB, TPB>>>(C, A, 256);
    k_gcn_agg<<<(EE * 64 + TPB - 1) / TPB, TPB>>>(src, dst, C, A, 64);
    k_bias_relu<<<(NN * 256 + TPB - 1) / TPB, TPB>>>(A, gcn1_b, B, 256);

    // GCN2
    launch_gemm(NN, 128, 256, B, 256, gcn2_W, 128, gcn2_W, 128, D, 128, nullptr, 0);
    k_gcn_init<<<(NN * 128 + TPB - 1) / TPB, TPB>>>(D, E, 128);
    k_gcn_agg<<<(EE * 32 + TPB - 1) / TPB, TPB>>>(src, dst, D, E, 32);
    k_bias_relu<<<(NN * 128 + TPB - 1) / TPB, TPB>>>(E, gcn2_b, D, 128);

    // fc1 / fc2
    launch_gemm(NN, 128, 128, D, 128, fc1_W, 128, fc1_W, 128, E, 128, fc1_b, 1);
    launch_gemm(NN, 128, 128, E, 128, fc2_W, 128, fc2_W, 128, C, 128, fc2_b, 1);

    // round h5, then output head: 4096 x 16384 x 128 tf32 tensor cores
    k_round<<<(NN * 128 / 4 + TPB - 1) / TPB, TPB>>>(C, Ht, NN * 128 / 4);
    {
        dim3 grid(16384 / 128, NN / 128);
        gemm_tf32f<128, 64, 32><<<grid, 256>>>(NN, 16384, 128, Ht, 128, OWt, 16384,
                                               out, 16384, out_b);
    }
}

// round 5
// speedup vs baseline: 1.8129x; 1.8129x over previous
#include <cuda_runtime.h>
#include <cuda_bf16.h>
#include <math.h>
#include <stdint.h>

#define NN 4096
#define EE 65536

// ------------------- scratch (static device globals; no allocs) -------------
__device__ float g_P[NN * 512];
__device__ float g_A[NN * 256];
__device__ float g_B[NN * 256];
__device__ float g_C[NN * 256];
__device__ float g_D[NN * 128];
__device__ float g_E[NN * 128];
__device__ int   g_cnt[NN];
__device__ float g_dinv[NN];
// packed (tf32-rounded, fragment-tile-major) operands
__device__ float g_Xt[NN * NN];      // x packed   (A of P-GEMM)
__device__ float g_Wt[NN * 512];     // [Wl|Wr] packed (B of P-GEMM, BN=64)
__device__ float g_Ht[NN * 128];     // h5 packed  (A of head GEMM)
__device__ float g_OWt[128 * 16384]; // out_W packed (B of head GEMM, BN=128)

__device__ __forceinline__ float rtf32(float f) {
    uint32_t r;
    asm("cvt.rna.tf32.f32 %0, %1;" : "=r"(r) : "f"(f));
    return __uint_as_float(r);
}

// ------------------------------- utility kernels ----------------------------
__global__ void k_zero_cnt() {
    int i = blockIdx.x * blockDim.x + threadIdx.x;
    if (i < NN) g_cnt[i] = 0;
}
__global__ void k_count(const int* __restrict__ dst) {
    int e = blockIdx.x * blockDim.x + threadIdx.x;
    if (e < EE) atomicAdd(&g_cnt[dst[e]], 1);
}
__global__ void k_dinv() {
    int i = blockIdx.x * blockDim.x + threadIdx.x;
    if (i < NN) g_dinv[i] = rsqrtf((float)(g_cnt[i] + 1));
}
__global__ void k_zero_f(float* __restrict__ p, int n) {
    int i = blockIdx.x * blockDim.x + threadIdx.x;
    if (i < n) p[i] = 0.0f;
}

// ---- pack A operand: round to tf32 + permute to fragment-tile-major --------
// Layout: for row-block br (128 rows), k-tile t (16 cols): 512 float4 chunk.
// float4 index within tile: q = s*256 + t8*32 + lane  (s=k-slice, t8=m-subtile)
//   m = br*128 + t8*16 + (lane>>2) (+8 for .y/.w),  k = t*16 + s*8 + (lane&3) (+4 for .z/.w)
__global__ void k_packA(const float* __restrict__ in, float* __restrict__ out,
                        int M, int K, int lda) {
    int o = blockIdx.x * blockDim.x + threadIdx.x;
    int total = (M * K) >> 2;
    if (o >= total) return;
    int perBlk = (K >> 4) << 9;           // (K/16)*512
    int br = o / perBlk;
    int r = o - br * perBlk;
    int t = r >> 9;
    int q = r & 511;
    int s = q >> 8;
    int t8 = (q >> 5) & 7;
    int lane = q & 31;
    int m = br * 128 + t8 * 16 + (lane >> 2);
    int k = t * 16 + s * 8 + (lane & 3);
    const float* base = in + (size_t)m * lda + k;
    float4 v;
    v.x = rtf32(base[0]);
    v.y = rtf32(base[(size_t)8 * lda]);
    v.z = rtf32(base[4]);
    v.w = rtf32(base[(size_t)8 * lda + 4]);
    ((float4*)out)[o] = v;
}

// ---- pack B operand: round + permute, fragment-tile-major ------------------
// For col-block bc (BN cols), k-tile t: BN*8 float2 chunk.
// float2 index within tile: r2 = s*(BN*4) + u*32 + lane
//   k = t*16 + s*8 + (lane&3) (+4 for .y),  n = bc*BN + u*8 + (lane>>2)
__global__ void k_packB(const float* __restrict__ B0, const float* __restrict__ B1,
                        int nsplit, int K, int N, int ldb, int BN,
                        float* __restrict__ out) {
    int o = blockIdx.x * blockDim.x + threadIdx.x;
    int total = (K * N) >> 1;
    if (o >= total) return;
    int perBc = (K * BN) >> 1;
    int bc = o / perBc;
    int r = o - bc * perBc;
    int perTile = BN * 8;
    int t = r / perTile;
    int q = r - t * perTile;
    int s = q / (BN * 4);
    int q2 = q - s * (BN * 4);
    int u = q2 >> 5;
    int lane = q2 & 31;
    int k = t * 16 + s * 8 + (lane & 3);
    int n = bc * BN + u * 8 + (lane >> 2);
    const float* src = B0;
    if (n >= nsplit) { src = B1; n -= nsplit; }
    float2 v;
    v.x = rtf32(src[(size_t)k * ldb + n]);
    v.y = rtf32(src[(size_t)(k + 4) * ldb + n]);
    ((float2*)out)[o] = v;
}

__global__ void k_sage_agg(const int* __restrict__ src, const int* __restrict__ dst) {
    int t = blockIdx.x * blockDim.x + threadIdx.x;
    if (t >= EE * 64) return;
    int e = t >> 6;
    int q = t & 63;
    int s = src[e];
    int d = dst[e];
    float4 v = ((const float4*)(g_P + (size_t)s * 512))[q];
    float* out = g_A + (size_t)d * 256 + q * 4;
    atomicAdd(out + 0, v.x);
    atomicAdd(out + 1, v.y);
    atomicAdd(out + 2, v.z);
    atomicAdd(out + 3, v.w);
}
__global__ void k_sage_combine(const float* __restrict__ bl) {
    int i = blockIdx.x * blockDim.x + threadIdx.x;
    if (i >= NN * 256) return;
    int v = i >> 8;
    int c = i & 255;
    float inv = 1.0f / fmaxf((float)g_cnt[v], 1.0f);
    float val = g_A[i] * inv + bl[c] + g_P[(size_t)v * 512 + 256 + c];
    g_B[i] = fmaxf(val, 0.0f);
}
__global__ void k_gcn_init(const float* __restrict__ hw, float* __restrict__ agg, int H) {
    int i = blockIdx.x * blockDim.x + threadIdx.x;
    if (i >= NN * H) return;
    int v = i / H;
    float dv = g_dinv[v];
    agg[i] = dv * dv * hw[i];
}
__global__ void k_gcn_agg(const int* __restrict__ src, const int* __restrict__ dst,
                          const float* __restrict__ hw, float* __restrict__ agg, int Hq) {
    int t = blockIdx.x * blockDim.x + threadIdx.x;
    if (t >= EE * Hq) return;
    int e = t / Hq;
    int q = t - e * Hq;
    int s = src[e];
    int d = dst[e];
    float norm = g_dinv[s] * g_dinv[d];
    int H = Hq * 4;
    float4 v = ((const float4*)(hw + (size_t)s * H))[q];
    float* out = agg + (size_t)d * H + q * 4;
    atomicAdd(out + 0, norm * v.x);
    atomicAdd(out + 1, norm * v.y);
    atomicAdd(out + 2, norm * v.z);
    atomicAdd(out + 3, norm * v.w);
}
__global__ void k_bias_relu(const float* __restrict__ in, const float* __restrict__ b,
                            float* __restrict__ out, int H) {
    int i = blockIdx.x * blockDim.x + threadIdx.x;
    if (i >= NN * H) return;
    int c = i % H;
    out[i] = fmaxf(in[i] + b[c], 0.0f);
}

// ---------------------------- fp32 SIMT GEMM (small layers) -----------------
__global__ void __launch_bounds__(256, 2)
sgemm(int M, int N, int K,
      const float* __restrict__ A, int lda,
      const float* __restrict__ B, int ldb,
      const float* __restrict__ B2, int nsplit,
      float* __restrict__ C, int ldc,
      const float* __restrict__ bias, int do_relu)
{
    const int BK = 8;
    __shared__ float As[2][BK][128];
    __shared__ float Bs[2][BK][128];

    int tid = threadIdx.x;
    int tx = tid & 15;
    int ty = tid >> 4;
    int row0 = blockIdx.y * 128;
    int col0 = blockIdx.x * 128;

    const float* Bp = B;
    int cb = col0;
    if (col0 >= nsplit) { Bp = B2; cb = col0 - nsplit; }

    int am = tid >> 1;
    int ak = (tid & 1) << 2;
    int bk = tid >> 5;
    int bn = (tid & 31) << 2;

    const float* Aptr = A + (size_t)(row0 + am) * lda + ak;
    const float* Bptr = Bp + (size_t)bk * ldb + cb + bn;
    size_t bstep = (size_t)BK * ldb;

    float4 av = *(const float4*)Aptr;
    float4 bv = *(const float4*)Bptr;
    As[0][ak + 0][am] = av.x;
    As[0][ak + 1][am] = av.y;
    As[0][ak + 2][am] = av.z;
    As[0][ak + 3][am] = av.w;
    *(float4*)&Bs[0][bk][bn] = bv;
    __syncthreads();

    float acc[8][8];
    #pragma unroll
    for (int i = 0; i < 8; i++)
        #pragma unroll
        for (int j = 0; j < 8; j++) acc[i][j] = 0.0f;

    int ntiles = K / BK;
    for (int t = 0; t < ntiles; t++) {
        int buf = t & 1;
        if (t + 1 < ntiles) {
            av = *(const float4*)(Aptr + (size_t)(t + 1) * BK);
            bv = *(const float4*)(Bptr + (size_t)(t + 1) * bstep);
        }
        #pragma unroll
        for (int k = 0; k < BK; k++) {
            float a[8], b[8];
            *(float4*)&a[0] = *(float4*)&As[buf][k][ty * 8];
            *(float4*)&a[4] = *(float4*)&As[buf][k][ty * 8 + 4];
            *(float4*)&b[0] = *(float4*)&Bs[buf][k][tx * 8];
            *(float4*)&b[4] = *(float4*)&Bs[buf][k][tx * 8 + 4];
            #pragma unroll
            for (int i = 0; i < 8; i++)
                #pragma unroll
                for (int j = 0; j < 8; j++)
                    acc[i][j] = fmaf(a[i], b[j], acc[i][j]);
        }
        if (t + 1 < ntiles) {
            int nb = buf ^ 1;
            As[nb][ak + 0][am] = av.x;
            As[nb][ak + 1][am] = av.y;
            As[nb][ak + 2][am] = av.z;
            As[nb][ak + 3][am] = av.w;
            *(float4*)&Bs[nb][bk][bn] = bv;
            __syncthreads();
        }
    }

    #pragma unroll
    for (int i = 0; i < 8; i++) {
        int gm = row0 + ty * 8 + i;
        #pragma unroll
        for (int j = 0; j < 8; j += 4) {
            int gn = col0 + tx * 8 + j;
            float4 v;
            v.x = acc[i][j + 0];
            v.y = acc[i][j + 1];
            v.z = acc[i][j + 2];
            v.w = acc[i][j + 3];
            if (bias) {
                v.x += bias[gn + 0];
                v.y += bias[gn + 1];
                v.z += bias[gn + 2];
                v.w += bias[gn + 3];
            }
            if (do_relu) {
                v.x = fmaxf(v.x, 0.0f);
                v.y = fmaxf(v.y, 0.0f);
                v.z = fmaxf(v.z, 0.0f);
                v.w = fmaxf(v.w, 0.0f);
            }
            *(float4*)&C[(size_t)gm * ldc + gn] = v;
        }
    }
}

// ------------- tf32 tensor-core GEMM on pre-packed operands -----------------
// At: fragment-tile-major A (see k_packA), Bt: fragment-tile-major B (k_packB).
// Global->smem is a linear float4 copy; fragments load as LDS.128/LDS.64.

__device__ __forceinline__ void mma_tf32(float* c, const uint32_t* a, const uint32_t* b) {
    asm volatile(
        "mma.sync.aligned.m16n8k8.row.col.f32.tf32.tf32.f32 "
        "{%0,%1,%2,%3}, {%4,%5,%6,%7}, {%8,%9}, {%0,%1,%2,%3};"
        : "+f"(c[0]), "+f"(c[1]), "+f"(c[2]), "+f"(c[3])
        : "r"(a[0]), "r"(a[1]), "r"(a[2]), "r"(a[3]), "r"(b[0]), "r"(b[1]));
}

template<int BN, int WM, int WN>
__global__ void __launch_bounds__(256, 2)
gemm_tf32p(int M, int N, int K,
           const float* __restrict__ At,
           const float* __restrict__ Bt,
           float* __restrict__ C, int ldc,
           const float* __restrict__ bias)
{
    const int MFRAG = WM / 16;
    const int NFRAG = WN / 8;
    const int WARPS_N = BN / WN;
    const int ATILE = 2048;         // floats per A k-tile (128x16)
    const int BTILE = 16 * BN;      // floats per B k-tile
    const int NB4 = BTILE / 4 / 256;

    __shared__ float AsF[2][ATILE];
    __shared__ float BsF[2][BTILE];

    int tid = threadIdx.x;
    int lane = tid & 31;
    int warp = tid >> 5;
    int warp_m = warp / WARPS_N;
    int warp_n = warp % WARPS_N;

    int br = blockIdx.y;
    int bc = blockIdx.x;
    int ktiles = K >> 4;

    const float4* Ab = (const float4*)(At + (size_t)br * ktiles * ATILE);
    const float4* Bb = (const float4*)(Bt + (size_t)bc * ktiles * BTILE);

    float4 avp[2], bvp[2];
    avp[0] = Ab[tid];
    avp[1] = Ab[tid + 256];
    #pragma unroll
    for (int l = 0; l < NB4; l++) bvp[l] = Bb[tid + l * 256];

    ((float4*)AsF[0])[tid]       = avp[0];
    ((float4*)AsF[0])[tid + 256] = avp[1];
    #pragma unroll
    for (int l = 0; l < NB4; l++) ((float4*)BsF[0])[tid + l * 256] = bvp[l];
    __syncthreads();

    float acc[MFRAG][NFRAG][4];
    #pragma unroll
    for (int mi = 0; mi < MFRAG; mi++)
        #pragma unroll
        for (int ni = 0; ni < NFRAG; ni++)
            #pragma unroll
            for (int j = 0; j < 4; j++) acc[mi][ni][j] = 0.0f;

    for (int t = 0; t < ktiles; t++) {
        int buf = t & 1;
        if (t + 1 < ktiles) {
            const float4* An = Ab + (size_t)(t + 1) * (ATILE / 4);
            const float4* Bn = Bb + (size_t)(t + 1) * (BTILE / 4);
            avp[0] = An[tid];
            avp[1] = An[tid + 256];
            #pragma unroll
            for (int l = 0; l < NB4; l++) bvp[l] = Bn[tid + l * 256];
        }

        #pragma unroll
        for (int s = 0; s < 2; s++) {
            uint32_t afr[MFRAG][4];
            uint32_t bfr[NFRAG][2];
            #pragma unroll
            for (int mi = 0; mi < MFRAG; mi++) {
                int t8 = warp_m * MFRAG + mi;
                float4 fa = *(const float4*)&AsF[buf][(((s << 3) + t8) * 32 + lane) * 4];
                afr[mi][0] = __float_as_uint(fa.x);
                afr[mi][1] = __float_as_uint(fa.y);
                afr[mi][2] = __float_as_uint(fa.z);
                afr[mi][3] = __float_as_uint(fa.w);
            }
            #pragma unroll
            for (int ni = 0; ni < NFRAG; ni++) {
                int u = warp_n * NFRAG + ni;
                float2 fb = *(const float2*)&BsF[buf][((s * (BN / 8) + u) * 32 + lane) * 2];
                bfr[ni][0] = __float_as_uint(fb.x);
                bfr[ni][1] = __float_as_uint(fb.y);
            }
            #pragma unroll
            for (int mi = 0; mi < MFRAG; mi++)
                #pragma unroll
                for (int ni = 0; ni < NFRAG; ni++)
                    mma_tf32(acc[mi][ni], afr[mi], bfr[ni]);
        }

        if (t + 1 < ktiles) {
            int nb = buf ^ 1;
            ((float4*)AsF[nb])[tid]       = avp[0];
            ((float4*)AsF[nb])[tid + 256] = avp[1];
            #pragma unroll
            for (int l = 0; l < NB4; l++) ((float4*)BsF[nb])[tid + l * 256] = bvp[l];
            __syncthreads();
        }
    }

    int qm = lane >> 2;
    int qk = lane & 3;
    #pragma unroll
    for (int mi = 0; mi < MFRAG; mi++) {
        int r = br * 128 + warp_m * WM + mi * 16 + qm;
        #pragma unroll
        for (int ni = 0; ni < NFRAG; ni++) {
            int c = bc * BN + warp_n * WN + ni * 8 + 2 * qk;
            float2 v0 = make_float2(acc[mi][ni][0], acc[mi][ni][1]);
            float2 v1 = make_float2(acc[mi][ni][2], acc[mi][ni][3]);
            if (bias) {
                float2 bb = *(const float2*)&bias[c];
                v0.x += bb.x; v0.y += bb.y;
                v1.x += bb.x; v1.y += bb.y;
            }
            *(float2*)&C[(size_t)r * ldc + c] = v0;
            *(float2*)&C[(size_t)(r + 8) * ldc + c] = v1;
        }
    }
}

// ------------------------------ host orchestration ---------------------------
static void launch_gemm(int M, int N, int K,
                        const float* A, int lda,
                        const float* B, int ldb,
                        const float* B2, int nsplit,
                        float* C, int ldc,
                        const float* bias, int do_relu)
{
    dim3 grid(N / 128, M / 128);
    sgemm<<<grid, 256>>>(M, N, K, A, lda, B, ldb, B2, nsplit, C, ldc, bias, do_relu);
}

extern "C" void kernel_launch(void* const* d_in, const int* in_sizes, int n_in,
                              void* d_out, int out_size)
{
    const float* x       = (const float*)d_in[0];
    const int*   eidx    = (const int*)  d_in[1];
    const float* sage_Wl = (const float*)d_in[2];
    const float* sage_bl = (const float*)d_in[3];
    const float* sage_Wr = (const float*)d_in[4];
    const float* gcn1_W  = (const float*)d_in[5];
    const float* gcn1_b  = (const float*)d_in[6];
    const float* gcn2_W  = (const float*)d_in[7];
    const float* gcn2_b  = (const float*)d_in[8];
    const float* fc1_W   = (const float*)d_in[9];
    const float* fc1_b   = (const float*)d_in[10];
    const float* fc2_W   = (const float*)d_in[11];
    const float* fc2_b   = (const float*)d_in[12];
    const float* out_W   = (const float*)d_in[13];
    const float* out_b   = (const float*)d_in[14];
    float* out = (float*)d_out;

    const int* src = eidx;
    const int* dst = eidx + EE;

    float *P, *A, *B, *C, *D, *E, *Xt, *Wt, *Ht, *OWt;
    cudaGetSymbolAddress((void**)&P, g_P);
    cudaGetSymbolAddress((void**)&A, g_A);
    cudaGetSymbolAddress((void**)&B, g_B);
    cudaGetSymbolAddress((void**)&C, g_C);
    cudaGetSymbolAddress((void**)&D, g_D);
    cudaGetSymbolAddress((void**)&E, g_E);
    cudaGetSymbolAddress((void**)&Xt, g_Xt);
    cudaGetSymbolAddress((void**)&Wt, g_Wt);
    cudaGetSymbolAddress((void**)&Ht, g_Ht);
    cudaGetSymbolAddress((void**)&OWt, g_OWt);

    const int TPB = 256;

    k_zero_cnt<<<(NN + TPB - 1) / TPB, TPB>>>();
    k_count<<<(EE + TPB - 1) / TPB, TPB>>>(dst);
    k_dinv<<<(NN + TPB - 1) / TPB, TPB>>>();

    // pack operands of the big GEMMs (round to tf32 + fragment-tile-major)
    k_packA<<<NN * NN / 4 / TPB, TPB>>>(x, Xt, NN, NN, NN);
    k_packB<<<NN * 512 / 2 / TPB, TPB>>>(sage_Wl, sage_Wr, 256, NN, 512, 256, 64, Wt);
    k_packB<<<128 * 16384 / 2 / TPB, TPB>>>(out_W, out_W, 16384, 128, 16384, 16384, 128, OWt);

    // P = x @ [Wl | Wr]  (4096 x 512 x 4096), BN=64 -> grid 256
    {
        dim3 grid(512 / 64, NN / 128);
        gemm_tf32p<64, 32, 32><<<grid, 256>>>(NN, 512, NN, Xt, Wt, P, 512, nullptr);
    }

    // SAGE
    k_zero_f<<<(NN * 256 + TPB - 1) / TPB, TPB>>>(A, NN * 256);
    k_sage_agg<<<(EE * 64 + TPB - 1) / TPB, TPB>>>(src, dst);
    k_sage_combine<<<(NN * 256 + TPB - 1) / TPB, TPB>>>(sage_bl);

    // GCN1 (fp32 SIMT)
    launch_gemm(NN, 256, 256, B, 256, gcn1_W, 256, gcn1_W, 256, C, 256, nullptr, 0);
    k_gcn_init<<<(NN * 256 + TPB - 1) / TPB, TPB>>>(C, A, 256);
    k_gcn_agg<<<(EE * 64 + TPB - 1) / TPB, TPB>>>(src, dst, C, A, 64);
    k_bias_relu<<<(NN * 256 + TPB - 1) / TPB, TPB>>>(A, gcn1_b, B, 256);

    // GCN2
    launch_gemm(NN, 128, 256, B, 256, gcn2_W, 128, gcn2_W, 128, D, 128, nullptr, 0);
    k_gcn_init<<<(NN * 128 + TPB - 1) / TPB, TPB>>>(D, E, 128);
    k_gcn_agg<<<(EE * 32 + TPB - 1) / TPB, TPB>>>(src, dst, D, E, 32);
    k_bias_relu<<<(NN * 128 + TPB - 1) / TPB, TPB>>>(E, gcn2_b, D, 128);

    // fc1 / fc2
    launch_gemm(NN, 128, 128, D, 128, fc1_W, 128, fc1_W, 128, E, 128, fc1_b, 1);
    launch_gemm(NN, 128, 128, E, 128, fc2_W, 128, fc2_W, 128, C, 128, fc2_b, 1);

    // pack h5, then output head: 4096 x 16384 x 128, BN=128 -> grid 4096
    k_packA<<<NN * 128 / 4 / TPB, TPB>>>(C, Ht, NN, 128, 128);
    {
        dim3 grid(16384 / 128, NN / 128);
        gemm_tf32p<128, 64, 32><<<grid, 256>>>(NN, 16384, 128, Ht, OWt, out, 16384, out_b);
    }
}

// round 6
// speedup vs baseline: 2.0458x; 1.1284x over previous
#include <cuda_runtime.h>
#include <cuda_bf16.h>
#include <math.h>
#include <stdint.h>

#define NN 4096
#define EE 65536

// ------------------- scratch (static device globals; no allocs) -------------
__device__ float g_P[NN * 512];
__device__ float g_A[NN * 256];
__device__ float g_B[NN * 256];
__device__ float g_C[NN * 256];
__device__ float g_D[NN * 128];
__device__ float g_E[NN * 128];
__device__ int   g_cnt[NN];
__device__ float g_dinv[NN];
// packed (tf32-rounded, fragment-tile-major) operands
__device__ float g_Xt[NN * NN];
__device__ float g_Wt[NN * 512];
__device__ float g_Ht[NN * 128];
__device__ float g_OWt[128 * 16384];

__device__ __forceinline__ float rtf32(float f) {
    uint32_t r;
    asm("cvt.rna.tf32.f32 %0, %1;" : "=r"(r) : "f"(f));
    return __uint_as_float(r);
}

// ------------------------------- utility kernels ----------------------------
__global__ void k_zero_cnt() {
    int i = blockIdx.x * blockDim.x + threadIdx.x;
    if (i < NN) g_cnt[i] = 0;
}
__global__ void k_count(const int* __restrict__ dst) {
    int e = blockIdx.x * blockDim.x + threadIdx.x;
    if (e < EE) atomicAdd(&g_cnt[dst[e]], 1);
}
__global__ void k_dinv() {
    int i = blockIdx.x * blockDim.x + threadIdx.x;
    if (i < NN) g_dinv[i] = rsqrtf((float)(g_cnt[i] + 1));
}
__global__ void k_zero_f(float* __restrict__ p, int n) {
    int i = blockIdx.x * blockDim.x + threadIdx.x;
    if (i < n) p[i] = 0.0f;
}

// ---- pack A operand: round to tf32 + permute to fragment-tile-major --------
__global__ void k_packA(const float* __restrict__ in, float* __restrict__ out,
                        int M, int K, int lda) {
    int o = blockIdx.x * blockDim.x + threadIdx.x;
    int total = (M * K) >> 2;
    if (o >= total) return;
    int perBlk = (K >> 4) << 9;           // (K/16)*512
    int br = o / perBlk;
    int r = o - br * perBlk;
    int t = r >> 9;
    int q = r & 511;
    int s = q >> 8;
    int t8 = (q >> 5) & 7;
    int lane = q & 31;
    int m = br * 128 + t8 * 16 + (lane >> 2);
    int k = t * 16 + s * 8 + (lane & 3);
    const float* base = in + (size_t)m * lda + k;
    float4 v;
    v.x = rtf32(base[0]);
    v.y = rtf32(base[(size_t)8 * lda]);
    v.z = rtf32(base[4]);
    v.w = rtf32(base[(size_t)8 * lda + 4]);
    ((float4*)out)[o] = v;
}

// ---- pack B operand: round + permute, fragment-tile-major ------------------
__global__ void k_packB(const float* __restrict__ B0, const float* __restrict__ B1,
                        int nsplit, int K, int N, int ldb, int BN,
                        float* __restrict__ out) {
    int o = blockIdx.x * blockDim.x + threadIdx.x;
    int total = (K * N) >> 1;
    if (o >= total) return;
    int perBc = (K * BN) >> 1;
    int bc = o / perBc;
    int r = o - bc * perBc;
    int perTile = BN * 8;
    int t = r / perTile;
    int q = r - t * perTile;
    int s = q / (BN * 4);
    int q2 = q - s * (BN * 4);
    int u = q2 >> 5;
    int lane = q2 & 31;
    int k = t * 16 + s * 8 + (lane & 3);
    int n = bc * BN + u * 8 + (lane >> 2);
    const float* src = B0;
    if (n >= nsplit) { src = B1; n -= nsplit; }
    float2 v;
    v.x = rtf32(src[(size_t)k * ldb + n]);
    v.y = rtf32(src[(size_t)(k + 4) * ldb + n]);
    ((float2*)out)[o] = v;
}

__global__ void k_sage_agg(const int* __restrict__ src, const int* __restrict__ dst) {
    int t = blockIdx.x * blockDim.x + threadIdx.x;
    if (t >= EE * 64) return;
    int e = t >> 6;
    int q = t & 63;
    int s = src[e];
    int d = dst[e];
    float4 v = ((const float4*)(g_P + (size_t)s * 512))[q];
    float* out = g_A + (size_t)d * 256 + q * 4;
    atomicAdd(out + 0, v.x);
    atomicAdd(out + 1, v.y);
    atomicAdd(out + 2, v.z);
    atomicAdd(out + 3, v.w);
}
__global__ void k_sage_combine(const float* __restrict__ bl) {
    int i = blockIdx.x * blockDim.x + threadIdx.x;
    if (i >= NN * 256) return;
    int v = i >> 8;
    int c = i & 255;
    float inv = 1.0f / fmaxf((float)g_cnt[v], 1.0f);
    float val = g_A[i] * inv + bl[c] + g_P[(size_t)v * 512 + 256 + c];
    g_B[i] = fmaxf(val, 0.0f);
}
__global__ void k_gcn_agg(const int* __restrict__ src, const int* __restrict__ dst,
                          const float* __restrict__ hw, float* __restrict__ agg, int Hq) {
    int t = blockIdx.x * blockDim.x + threadIdx.x;
    if (t >= EE * Hq) return;
    int e = t / Hq;
    int q = t - e * Hq;
    int s = src[e];
    int d = dst[e];
    float norm = g_dinv[s] * g_dinv[d];
    int H = Hq * 4;
    float4 v = ((const float4*)(hw + (size_t)s * H))[q];
    float* out = agg + (size_t)d * H + q * 4;
    atomicAdd(out + 0, norm * v.x);
    atomicAdd(out + 1, norm * v.y);
    atomicAdd(out + 2, norm * v.z);
    atomicAdd(out + 3, norm * v.w);
}
__global__ void k_bias_relu(const float* __restrict__ in, const float* __restrict__ b,
                            float* __restrict__ out, int H) {
    int i = blockIdx.x * blockDim.x + threadIdx.x;
    if (i >= NN * H) return;
    int c = i % H;
    out[i] = fmaxf(in[i] + b[c], 0.0f);
}

// ------------------- fp32 SIMT GEMM, 64x64x16 tiles (small layers) ----------
// C = A@B (+bias)(+relu). If C2 != null: also write C2 = dinv[row]^2 * val
// (GCN self-loop init) and C gets the raw val (no bias/relu).
__global__ void __launch_bounds__(256, 4)
sgemm64(int M, int N, int K,
        const float* __restrict__ A, int lda,
        const float* __restrict__ B, int ldb,
        float* __restrict__ C, int ldc,
        const float* __restrict__ bias, int do_relu,
        float* __restrict__ C2)
{
    const int BK = 16;
    __shared__ float As[2][BK][64];
    __shared__ float Bs[2][BK][64];

    int tid = threadIdx.x;
    int tx = tid & 15;     // 16 col-groups * 4
    int ty = tid >> 4;     // 16 row-groups * 4
    int row0 = blockIdx.y * 64;
    int col0 = blockIdx.x * 64;

    int am = tid >> 2;           // 0..63
    int ak = (tid & 3) << 2;     // 0,4,8,12
    int bk = tid >> 4;           // 0..15
    int bn = (tid & 15) << 2;    // 0..60

    const float* Aptr = A + (size_t)(row0 + am) * lda + ak;
    const float* Bptr = B + (size_t)bk * ldb + col0 + bn;
    size_t bstep = (size_t)BK * ldb;

    float4 av = *(const float4*)Aptr;
    float4 bv = *(const float4*)Bptr;
    As[0][ak + 0][am] = av.x;
    As[0][ak + 1][am] = av.y;
    As[0][ak + 2][am] = av.z;
    As[0][ak + 3][am] = av.w;
    *(float4*)&Bs[0][bk][bn] = bv;
    __syncthreads();

    float acc[4][4];
    #pragma unroll
    for (int i = 0; i < 4; i++)
        #pragma unroll
        for (int j = 0; j < 4; j++) acc[i][j] = 0.0f;

    int ntiles = K / BK;
    for (int t = 0; t < ntiles; t++) {
        int buf = t & 1;
        if (t + 1 < ntiles) {
            av = *(const float4*)(Aptr + (size_t)(t + 1) * BK);
            bv = *(const float4*)(Bptr + (size_t)(t + 1) * bstep);
        }
        #pragma unroll
        for (int k = 0; k < BK; k++) {
            float a[4], b[4];
            *(float4*)&a[0] = *(float4*)&As[buf][k][ty * 4];
            *(float4*)&b[0] = *(float4*)&Bs[buf][k][tx * 4];
            #pragma unroll
            for (int i = 0; i < 4; i++)
                #pragma unroll
                for (int j = 0; j < 4; j++)
                    acc[i][j] = fmaf(a[i], b[j], acc[i][j]);
        }
        if (t + 1 < ntiles) {
            int nb = buf ^ 1;
            As[nb][ak + 0][am] = av.x;
            As[nb][ak + 1][am] = av.y;
            As[nb][ak + 2][am] = av.z;
            As[nb][ak + 3][am] = av.w;
            *(float4*)&Bs[nb][bk][bn] = bv;
            __syncthreads();
        }
    }

    #pragma unroll
    for (int i = 0; i < 4; i++) {
        int gm = row0 + ty * 4 + i;
        int gn = col0 + tx * 4;
        float4 v = make_float4(acc[i][0], acc[i][1], acc[i][2], acc[i][3]);
        if (C2) {
            *(float4*)&C[(size_t)gm * ldc + gn] = v;
            float dv = g_dinv[gm];
            float s = dv * dv;
            float4 w = make_float4(s * v.x, s * v.y, s * v.z, s * v.w);
            *(float4*)&C2[(size_t)gm * ldc + gn] = w;
        } else {
            if (bias) {
                v.x += bias[gn + 0];
                v.y += bias[gn + 1];
                v.z += bias[gn + 2];
                v.w += bias[gn + 3];
            }
            if (do_relu) {
                v.x = fmaxf(v.x, 0.0f);
                v.y = fmaxf(v.y, 0.0f);
                v.z = fmaxf(v.z, 0.0f);
                v.w = fmaxf(v.w, 0.0f);
            }
            *(float4*)&C[(size_t)gm * ldc + gn] = v;
        }
    }
}

// ------------- tf32 tensor-core GEMM on pre-packed operands -----------------
__device__ __forceinline__ void mma_tf32(float* c, const uint32_t* a, const uint32_t* b) {
    asm volatile(
        "mma.sync.aligned.m16n8k8.row.col.f32.tf32.tf32.f32 "
        "{%0,%1,%2,%3}, {%4,%5,%6,%7}, {%8,%9}, {%0,%1,%2,%3};"
        : "+f"(c[0]), "+f"(c[1]), "+f"(c[2]), "+f"(c[3])
        : "r"(a[0]), "r"(a[1]), "r"(a[2]), "r"(a[3]), "r"(b[0]), "r"(b[1]));
}

template<int BN, int WM, int WN>
__global__ void __launch_bounds__(256, 2)
gemm_tf32p(int M, int N, int K,
           const float* __restrict__ At,
           const float* __restrict__ Bt,
           float* __restrict__ C, int ldc,
           const float* __restrict__ bias)
{
    const int MFRAG = WM / 16;
    const int NFRAG = WN / 8;
    const int WARPS_N = BN / WN;
    const int ATILE = 2048;
    const int BTILE = 16 * BN;
    const int NB4 = BTILE / 4 / 256;

    __shared__ float AsF[2][ATILE];
    __shared__ float BsF[2][BTILE];

    int tid = threadIdx.x;
    int lane = tid & 31;
    int warp = tid >> 5;
    int warp_m = warp / WARPS_N;
    int warp_n = warp % WARPS_N;

    int br = blockIdx.y;
    int bc = blockIdx.x;
    int ktiles = K >> 4;

    const float4* Ab = (const float4*)(At + (size_t)br * ktiles * ATILE);
    const float4* Bb = (const float4*)(Bt + (size_t)bc * ktiles * BTILE);

    float4 avp[2], bvp[2];
    avp[0] = Ab[tid];
    avp[1] = Ab[tid + 256];
    #pragma unroll
    for (int l = 0; l < NB4; l++) bvp[l] = Bb[tid + l * 256];

    ((float4*)AsF[0])[tid]       = avp[0];
    ((float4*)AsF[0])[tid + 256] = avp[1];
    #pragma unroll
    for (int l = 0; l < NB4; l++) ((float4*)BsF[0])[tid + l * 256] = bvp[l];
    __syncthreads();

    float acc[MFRAG][NFRAG][4];
    #pragma unroll
    for (int mi = 0; mi < MFRAG; mi++)
        #pragma unroll
        for (int ni = 0; ni < NFRAG; ni++)
            #pragma unroll
            for (int j = 0; j < 4; j++) acc[mi][ni][j] = 0.0f;

    for (int t = 0; t < ktiles; t++) {
        int buf = t & 1;
        if (t + 1 < ktiles) {
            const float4* An = Ab + (size_t)(t + 1) * (ATILE / 4);
            const float4* Bn = Bb + (size_t)(t + 1) * (BTILE / 4);
            avp[0] = An[tid];
            avp[1] = An[tid + 256];
            #pragma unroll
            for (int l = 0; l < NB4; l++) bvp[l] = Bn[tid + l * 256];
        }

        #pragma unroll
        for (int s = 0; s < 2; s++) {
            uint32_t afr[MFRAG][4];
            uint32_t bfr[NFRAG][2];
            #pragma unroll
            for (int mi = 0; mi < MFRAG; mi++) {
                int t8 = warp_m * MFRAG + mi;
                float4 fa = *(const float4*)&AsF[buf][(((s << 3) + t8) * 32 + lane) * 4];
                afr[mi][0] = __float_as_uint(fa.x);
                afr[mi][1] = __float_as_uint(fa.y);
                afr[mi][2] = __float_as_uint(fa.z);
                afr[mi][3] = __float_as_uint(fa.w);
            }
            #pragma unroll
            for (int ni = 0; ni < NFRAG; ni++) {
                int u = warp_n * NFRAG + ni;
                float2 fb = *(const float2*)&BsF[buf][((s * (BN / 8) + u) * 32 + lane) * 2];
                bfr[ni][0] = __float_as_uint(fb.x);
                bfr[ni][1] = __float_as_uint(fb.y);
            }
            #pragma unroll
            for (int mi = 0; mi < MFRAG; mi++)
                #pragma unroll
                for (int ni = 0; ni < NFRAG; ni++)
                    mma_tf32(acc[mi][ni], afr[mi], bfr[ni]);
        }

        if (t + 1 < ktiles) {
            int nb = buf ^ 1;
            ((float4*)AsF[nb])[tid]       = avp[0];
            ((float4*)AsF[nb])[tid + 256] = avp[1];
            #pragma unroll
            for (int l = 0; l < NB4; l++) ((float4*)BsF[nb])[tid + l * 256] = bvp[l];
            __syncthreads();
        }
    }

    int qm = lane >> 2;
    int qk = lane & 3;
    #pragma unroll
    for (int mi = 0; mi < MFRAG; mi++) {
        int r = br * 128 + warp_m * WM + mi * 16 + qm;
        #pragma unroll
        for (int ni = 0; ni < NFRAG; ni++) {
            int c = bc * BN + warp_n * WN + ni * 8 + 2 * qk;
            float2 v0 = make_float2(acc[mi][ni][0], acc[mi][ni][1]);
            float2 v1 = make_float2(acc[mi][ni][2], acc[mi][ni][3]);
            if (bias) {
                float2 bb = *(const float2*)&bias[c];
                v0.x += bb.x; v0.y += bb.y;
                v1.x += bb.x; v1.y += bb.y;
            }
            *(float2*)&C[(size_t)r * ldc + c] = v0;
            *(float2*)&C[(size_t)(r + 8) * ldc + c] = v1;
        }
    }
}

// ------------------------------ host orchestration ---------------------------
extern "C" void kernel_launch(void* const* d_in, const int* in_sizes, int n_in,
                              void* d_out, int out_size)
{
    const float* x       = (const float*)d_in[0];
    const int*   eidx    = (const int*)  d_in[1];
    const float* sage_Wl = (const float*)d_in[2];
    const float* sage_bl = (const float*)d_in[3];
    const float* sage_Wr = (const float*)d_in[4];
    const float* gcn1_W  = (const float*)d_in[5];
    const float* gcn1_b  = (const float*)d_in[6];
    const float* gcn2_W  = (const float*)d_in[7];
    const float* gcn2_b  = (const float*)d_in[8];
    const float* fc1_W   = (const float*)d_in[9];
    const float* fc1_b   = (const float*)d_in[10];
    const float* fc2_W   = (const float*)d_in[11];
    const float* fc2_b   = (const float*)d_in[12];
    const float* out_W   = (const float*)d_in[13];
    const float* out_b   = (const float*)d_in[14];
    float* out = (float*)d_out;

    const int* src = eidx;
    const int* dst = eidx + EE;

    float *P, *A, *B, *C, *D, *E, *Xt, *Wt, *Ht, *OWt;
    cudaGetSymbolAddress((void**)&P, g_P);
    cudaGetSymbolAddress((void**)&A, g_A);
    cudaGetSymbolAddress((void**)&B, g_B);
    cudaGetSymbolAddress((void**)&C, g_C);
    cudaGetSymbolAddress((void**)&D, g_D);
    cudaGetSymbolAddress((void**)&E, g_E);
    cudaGetSymbolAddress((void**)&Xt, g_Xt);
    cudaGetSymbolAddress((void**)&Wt, g_Wt);
    cudaGetSymbolAddress((void**)&Ht, g_Ht);
    cudaGetSymbolAddress((void**)&OWt, g_OWt);

    const int TPB = 256;

    k_zero_cnt<<<(NN + TPB - 1) / TPB, TPB>>>();
    k_count<<<(EE + TPB - 1) / TPB, TPB>>>(dst);
    k_dinv<<<(NN + TPB - 1) / TPB, TPB>>>();

    // pack operands of the big GEMMs
    k_packA<<<NN * NN / 4 / TPB, TPB>>>(x, Xt, NN, NN, NN);
    k_packB<<<NN * 512 / 2 / TPB, TPB>>>(sage_Wl, sage_Wr, 256, NN, 512, 256, 64, Wt);
    k_packB<<<128 * 16384 / 2 / TPB, TPB>>>(out_W, out_W, 16384, 128, 16384, 16384, 128, OWt);

    // P = x @ [Wl | Wr]  (4096 x 512 x 4096), tf32 tensor cores
    {
        dim3 grid(512 / 64, NN / 128);
        gemm_tf32p<64, 32, 32><<<grid, 256>>>(NN, 512, NN, Xt, Wt, P, 512, nullptr);
    }

    // SAGE
    k_zero_f<<<(NN * 256 + TPB - 1) / TPB, TPB>>>(A, NN * 256);
    k_sage_agg<<<(EE * 64 + TPB - 1) / TPB, TPB>>>(src, dst);
    k_sage_combine<<<(NN * 256 + TPB - 1) / TPB, TPB>>>(sage_bl);

    // GCN1: hw -> C, agg-init(dinv^2*hw) -> A, then edge agg + bias/relu -> B
    {
        dim3 grid(256 / 64, NN / 64);
        sgemm64<<<grid, 256>>>(NN, 256, 256, B, 256, gcn1_W, 256, C, 256, nullptr, 0, A);
    }
    k_gcn_agg<<<(EE * 64 + TPB - 1) / TPB, TPB>>>(src, dst, C, A, 64);
    k_bias_relu<<<(NN * 256 + TPB - 1) / TPB, TPB>>>(A, gcn1_b, B, 256);

    // GCN2: hw -> D, agg-init -> E
    {
        dim3 grid(128 / 64, NN / 64);
        sgemm64<<<grid, 256>>>(NN, 128, 256, B, 256, gcn2_W, 128, D, 128, nullptr, 0, E);
    }
    k_gcn_agg<<<(EE * 32 + TPB - 1) / TPB, TPB>>>(src, dst, D, E, 32);
    k_bias_relu<<<(NN * 128 + TPB - 1) / TPB, TPB>>>(E, gcn2_b, D, 128);

    // fc1 / fc2
    {
        dim3 grid(128 / 64, NN / 64);
        sgemm64<<<grid, 256>>>(NN, 128, 128, D, 128, fc1_W, 128, E, 128, fc1_b, 1, nullptr);
        sgemm64<<<grid, 256>>>(NN, 128, 128, E, 128, fc2_W, 128, C, 128, fc2_b, 1, nullptr);
    }

    // pack h5, then output head (4096 x 16384 x 128), tf32 tensor cores
    k_packA<<<NN * 128 / 4 / TPB, TPB>>>(C, Ht, NN, 128, 128);
    {
        dim3 grid(16384 / 128, NN / 128);
        gemm_tf32p<128, 64, 32><<<grid, 256>>>(NN, 16384, 128, Ht, OWt, out, 16384, out_b);
    }
}

// round 8
// speedup vs baseline: 2.4727x; 1.2087x over previous
#include <cuda_runtime.h>
#include <cuda_bf16.h>
#include <math.h>
#include <stdint.h>

#define NN 4096
#define EE 65536

// ------------------- scratch (static device globals; no allocs) -------------
__device__ float g_P[NN * 512];
__device__ float g_A[NN * 256];
__device__ float g_B[NN * 256];
__device__ float g_C[NN * 256];
__device__ float g_D[NN * 128];
__device__ float g_E[NN * 128];
__device__ int   g_cnt[NN];
__device__ float g_dinv[NN];
__device__ int   g_rowptr[NN + 1];
__device__ int   g_fill[NN];
__device__ int   g_adj[EE];
// packed (tf32-rounded, fragment-tile-major) operands
__device__ float g_Xt[NN * NN];
__device__ float g_Wt[NN * 512];
__device__ float g_Ht[NN * 128];
__device__ float g_OWt[128 * 16384];

__device__ __forceinline__ float rtf32(float f) {
    uint32_t r;
    asm("cvt.rna.tf32.f32 %0, %1;" : "=r"(r) : "f"(f));
    return __uint_as_float(r);
}

// ------------------------------- CSR build ----------------------------------
__global__ void k_zero_cnt() {
    int i = blockIdx.x * blockDim.x + threadIdx.x;
    if (i < NN) g_cnt[i] = 0;
}
__global__ void k_count(const int* __restrict__ dst) {
    int e = blockIdx.x * blockDim.x + threadIdx.x;
    if (e < EE) atomicAdd(&g_cnt[dst[e]], 1);
}
__global__ void k_dinv() {
    int i = blockIdx.x * blockDim.x + threadIdx.x;
    if (i < NN) g_dinv[i] = rsqrtf((float)(g_cnt[i] + 1));
}
// single block, 1024 threads, 4 counts each -> exclusive row pointers
__global__ void k_scan() {
    __shared__ int ts[1024];
    int t = threadIdx.x;
    int4 c = ((const int4*)g_cnt)[t];
    int s = c.x + c.y + c.z + c.w;
    ts[t] = s;
    __syncthreads();
    for (int off = 1; off < 1024; off <<= 1) {
        int x = (t >= off) ? ts[t - off] : 0;
        __syncthreads();
        ts[t] += x;
        __syncthreads();
    }
    int excl = ts[t] - s;
    int p0 = excl, p1 = excl + c.x, p2 = p1 + c.y, p3 = p2 + c.z;
    g_rowptr[4 * t + 0] = p0;  g_fill[4 * t + 0] = p0;
    g_rowptr[4 * t + 1] = p1;  g_fill[4 * t + 1] = p1;
    g_rowptr[4 * t + 2] = p2;  g_fill[4 * t + 2] = p2;
    g_rowptr[4 * t + 3] = p3;  g_fill[4 * t + 3] = p3;
    if (t == 1023) g_rowptr[NN] = ts[t];
}
__global__ void k_fill(const int* __restrict__ src, const int* __restrict__ dst) {
    int e = blockIdx.x * blockDim.x + threadIdx.x;
    if (e >= EE) return;
    int pos = atomicAdd(&g_fill[dst[e]], 1);
    g_adj[pos] = src[e];
}

// ---------------------- gather-based aggregations ----------------------------
// SAGE: h1[v] = relu(mean_{s in N(v)} Pl[s] + bl + Pr[v])  (256-dim, 64 f4 lanes)
__global__ void k_sage_gather(const float* __restrict__ bl) {
    int t = blockIdx.x * blockDim.x + threadIdx.x;
    if (t >= NN * 64) return;
    int v = t >> 6;
    int q = t & 63;
    int beg = g_rowptr[v], end = g_rowptr[v + 1];
    const float4* P4 = (const float4*)g_P;
    float4 acc = make_float4(0.f, 0.f, 0.f, 0.f);
    for (int i = beg; i < end; i++) {
        int s = g_adj[i];
        float4 p = P4[(size_t)s * 128 + q];
        acc.x += p.x; acc.y += p.y; acc.z += p.z; acc.w += p.w;
    }
    float inv = 1.0f / fmaxf((float)(end - beg), 1.0f);
    float4 b = ((const float4*)bl)[q];
    float4 pr = P4[(size_t)v * 128 + 64 + q];
    float4 r;
    r.x = fmaxf(acc.x * inv + b.x + pr.x, 0.f);
    r.y = fmaxf(acc.y * inv + b.y + pr.y, 0.f);
    r.z = fmaxf(acc.z * inv + b.z + pr.z, 0.f);
    r.w = fmaxf(acc.w * inv + b.w + pr.w, 0.f);
    ((float4*)g_B)[(size_t)v * 64 + q] = r;
}

// GCN: out[v] = relu(dinv[v]^2*hw[v] + sum dinv[v]dinv[s]*hw[s] + b), Hq f4 lanes
__global__ void k_gcn_gather(const float* __restrict__ hw, const float* __restrict__ bias,
                             float* __restrict__ out, int hqsh) {
    int t = blockIdx.x * blockDim.x + threadIdx.x;
    if (t >= (NN << hqsh)) return;
    int v = t >> hqsh;
    int q = t & ((1 << hqsh) - 1);
    int Hq = 1 << hqsh;
    int beg = g_rowptr[v], end = g_rowptr[v + 1];
    float dv = g_dinv[v];
    const float4* H4 = (const float4*)hw;
    float4 self = H4[(size_t)v * Hq + q];
    float dv2 = dv * dv;
    float4 acc = make_float4(dv2 * self.x, dv2 * self.y, dv2 * self.z, dv2 * self.w);
    for (int i = beg; i < end; i++) {
        int s = g_adj[i];
        float nm = dv * g_dinv[s];
        float4 p = H4[(size_t)s * Hq + q];
        acc.x += nm * p.x; acc.y += nm * p.y; acc.z += nm * p.z; acc.w += nm * p.w;
    }
    float4 b = ((const float4*)bias)[q];
    float4 r;
    r.x = fmaxf(acc.x + b.x, 0.f);
    r.y = fmaxf(acc.y + b.y, 0.f);
    r.z = fmaxf(acc.z + b.z, 0.f);
    r.w = fmaxf(acc.w + b.w, 0.f);
    ((float4*)out)[(size_t)v * Hq + q] = r;
}

// ---- pack A operand: round to tf32 + permute to fragment-tile-major --------
__global__ void k_packA(const float* __restrict__ in, float* __restrict__ out,
                        int M, int K, int lda) {
    int o = blockIdx.x * blockDim.x + threadIdx.x;
    int total = (M * K) >> 2;
    if (o >= total) return;
    int perBlk = (K >> 4) << 9;
    int br = o / perBlk;
    int r = o - br * perBlk;
    int t = r >> 9;
    int q = r & 511;
    int s = q >> 8;
    int t8 = (q >> 5) & 7;
    int lane = q & 31;
    int m = br * 128 + t8 * 16 + (lane >> 2);
    int k = t * 16 + s * 8 + (lane & 3);
    const float* base = in + (size_t)m * lda + k;
    float4 v;
    v.x = rtf32(base[0]);
    v.y = rtf32(base[(size_t)8 * lda]);
    v.z = rtf32(base[4]);
    v.w = rtf32(base[(size_t)8 * lda + 4]);
    ((float4*)out)[o] = v;
}

// ---- pack B operand, PAIRED n-fragments: one float4 per lane covers two
// adjacent n-tiles (cols u2*16..+15). x/y = frag 2u2 reg0/1, z/w = frag 2u2+1.
__global__ void k_packB(const float* __restrict__ B0, const float* __restrict__ B1,
                        int nsplit, int K, int N, int ldb, int BN,
                        float* __restrict__ out) {
    int o = blockIdx.x * blockDim.x + threadIdx.x;
    int total = (K * N) >> 2;
    if (o >= total) return;
    int perBc = (K * BN) >> 2;
    int bc = o / perBc;
    int r = o - bc * perBc;
    int perTile = BN * 4;              // float4s per k-tile (16 x BN / 4)
    int t = r / perTile;
    int q = r - t * perTile;
    int s = q / (BN * 2);
    int q2 = q - s * (BN * 2);
    int u2 = q2 >> 5;
    int lane = q2 & 31;
    int k = t * 16 + s * 8 + (lane & 3);
    int n = bc * BN + u2 * 16 + (lane >> 2);
    const float* src = B0;
    if (n >= nsplit) { src = B1; n -= nsplit; }
    float4 v;
    v.x = rtf32(src[(size_t)k * ldb + n]);
    v.y = rtf32(src[(size_t)(k + 4) * ldb + n]);
    v.z = rtf32(src[(size_t)k * ldb + n + 8]);
    v.w = rtf32(src[(size_t)(k + 4) * ldb + n + 8]);
    ((float4*)out)[o] = v;
}

// ------------------- fp32 SIMT GEMM, 64x64x16 tiles (small layers) ----------
__global__ void __launch_bounds__(256, 4)
sgemm64(int M, int N, int K,
        const float* __restrict__ A, int lda,
        const float* __restrict__ B, int ldb,
        float* __restrict__ C, int ldc,
        const float* __restrict__ bias, int do_relu)
{
    const int BK = 16;
    __shared__ float As[2][BK][64];
    __shared__ float Bs[2][BK][64];

    int tid = threadIdx.x;
    int tx = tid & 15;
    int ty = tid >> 4;
    int row0 = blockIdx.y * 64;
    int col0 = blockIdx.x * 64;

    int am = tid >> 2;
    int ak = (tid & 3) << 2;
    int bk = tid >> 4;
    int bn = (tid & 15) << 2;

    const float* Aptr = A + (size_t)(row0 + am) * lda + ak;
    const float* Bptr = B + (size_t)bk * ldb + col0 + bn;
    size_t bstep = (size_t)BK * ldb;

    float4 av = *(const float4*)Aptr;
    float4 bv = *(const float4*)Bptr;
    As[0][ak + 0][am] = av.x;
    As[0][ak + 1][am] = av.y;
    As[0][ak + 2][am] = av.z;
    As[0][ak + 3][am] = av.w;
    *(float4*)&Bs[0][bk][bn] = bv;
    __syncthreads();

    float acc[4][4];
    #pragma unroll
    for (int i = 0; i < 4; i++)
        #pragma unroll
        for (int j = 0; j < 4; j++) acc[i][j] = 0.0f;

    int ntiles = K / BK;
    for (int t = 0; t < ntiles; t++) {
        int buf = t & 1;
        if (t + 1 < ntiles) {
            av = *(const float4*)(Aptr + (size_t)(t + 1) * BK);
            bv = *(const float4*)(Bptr + (size_t)(t + 1) * bstep);
        }
        #pragma unroll
        for (int k = 0; k < BK; k++) {
            float a[4], b[4];
            *(float4*)&a[0] = *(float4*)&As[buf][k][ty * 4];
            *(float4*)&b[0] = *(float4*)&Bs[buf][k][tx * 4];
            #pragma unroll
            for (int i = 0; i < 4; i++)
                #pragma unroll
                for (int j = 0; j < 4; j++)
                    acc[i][j] = fmaf(a[i], b[j], acc[i][j]);
        }
        if (t + 1 < ntiles) {
            int nb = buf ^ 1;
            As[nb][ak + 0][am] = av.x;
            As[nb][ak + 1][am] = av.y;
            As[nb][ak + 2][am] = av.z;
            As[nb][ak + 3][am] = av.w;
            *(float4*)&Bs[nb][bk][bn] = bv;
            __syncthreads();
        }
    }

    #pragma unroll
    for (int i = 0; i < 4; i++) {
        int gm = row0 + ty * 4 + i;
        int gn = col0 + tx * 4;
        float4 v = make_float4(acc[i][0], acc[i][1], acc[i][2], acc[i][3]);
        if (bias) {
            v.x += bias[gn + 0];
            v.y += bias[gn + 1];
            v.z += bias[gn + 2];
            v.w += bias[gn + 3];
        }
        if (do_relu) {
            v.x = fmaxf(v.x, 0.0f);
            v.y = fmaxf(v.y, 0.0f);
            v.z = fmaxf(v.z, 0.0f);
            v.w = fmaxf(v.w, 0.0f);
        }
        *(float4*)&C[(size_t)gm * ldc + gn] = v;
    }
}

// ------------- mma.sync tf32 GEMM on pre-packed operands --------------------
__device__ __forceinline__ void mma_tf32(float* c, const uint32_t* a, const uint32_t* b) {
    asm volatile(
        "mma.sync.aligned.m16n8k8.row.col.f32.tf32.tf32.f32 "
        "{%0,%1,%2,%3}, {%4,%5,%6,%7}, {%8,%9}, {%0,%1,%2,%3};"
        : "+f"(c[0]), "+f"(c[1]), "+f"(c[2]), "+f"(c[3])
        : "r"(a[0]), "r"(a[1]), "r"(a[2]), "r"(a[3]), "r"(b[0]), "r"(b[1]));
}

template<int BN, int WM, int WN>
__global__ void __launch_bounds__(256, 2)
gemm_tf32p(int M, int N, int K,
           const float* __restrict__ At,
           const float* __restrict__ Bt,
           float* __restrict__ C, int ldc,
           const float* __restrict__ bias)
{
    const int MFRAG = WM / 16;
    const int NFRAG = WN / 8;
    const int WARPS_N = BN / WN;
    const int ATILE = 2048;
    const int BTILE = 16 * BN;
    const int NB4 = BTILE / 4 / 256;

    __shared__ float AsF[2][ATILE];
    __shared__ float BsF[2][BTILE];

    int tid = threadIdx.x;
    int lane = tid & 31;
    int warp = tid >> 5;
    int warp_m = warp / WARPS_N;
    int warp_n = warp % WARPS_N;

    int br = blockIdx.y;
    int bc = blockIdx.x;
    int ktiles = K >> 4;

    const float4* Ab = (const float4*)(At + (size_t)br * ktiles * ATILE);
    const float4* Bb = (const float4*)(Bt + (size_t)bc * ktiles * BTILE);

    float4 avp[2], bvp[2];
    avp[0] = Ab[tid];
    avp[1] = Ab[tid + 256];
    #pragma unroll
    for (int l = 0; l < NB4; l++) bvp[l] = Bb[tid + l * 256];

    ((float4*)AsF[0])[tid]       = avp[0];
    ((float4*)AsF[0])[tid + 256] = avp[1];
    #pragma unroll
    for (int l = 0; l < NB4; l++) ((float4*)BsF[0])[tid + l * 256] = bvp[l];
    __syncthreads();

    float acc[MFRAG][NFRAG][4];
    #pragma unroll
    for (int mi = 0; mi < MFRAG; mi++)
        #pragma unroll
        for (int ni = 0; ni < NFRAG; ni++)
            #pragma unroll
            for (int j = 0; j < 4; j++) acc[mi][ni][j] = 0.0f;

    for (int t = 0; t < ktiles; t++) {
        int buf = t & 1;
        if (t + 1 < ktiles) {
            const float4* An = Ab + (size_t)(t + 1) * (ATILE / 4);
            const float4* Bn = Bb + (size_t)(t + 1) * (BTILE / 4);
            avp[0] = An[tid];
            avp[1] = An[tid + 256];
            #pragma unroll
            for (int l = 0; l < NB4; l++) bvp[l] = Bn[tid + l * 256];
        }

        #pragma unroll
        for (int s = 0; s < 2; s++) {
            uint32_t afr[MFRAG][4];
            uint32_t bfr[NFRAG][2];
            #pragma unroll
            for (int mi = 0; mi < MFRAG; mi++) {
                int t8 = warp_m * MFRAG + mi;
                float4 fa = *(const float4*)&AsF[buf][(((s << 3) + t8) * 32 + lane) * 4];
                afr[mi][0] = __float_as_uint(fa.x);
                afr[mi][1] = __float_as_uint(fa.y);
                afr[mi][2] = __float_as_uint(fa.z);
                afr[mi][3] = __float_as_uint(fa.w);
            }
            // paired B fragments: one LDS.128 covers two n-tiles
            #pragma unroll
            for (int ni2 = 0; ni2 < NFRAG / 2; ni2++) {
                int u2 = warp_n * (WN / 16) + ni2;
                float4 fb = *(const float4*)&BsF[buf][((s * (BN / 16) + u2) * 32 + lane) * 4];
                bfr[2 * ni2][0]     = __float_as_uint(fb.x);
                bfr[2 * ni2][1]     = __float_as_uint(fb.y);
                bfr[2 * ni2 + 1][0] = __float_as_uint(fb.z);
                bfr[2 * ni2 + 1][1] = __float_as_uint(fb.w);
            }
            #pragma unroll
            for (int mi = 0; mi < MFRAG; mi++)
                #pragma unroll
                for (int ni = 0; ni < NFRAG; ni++)
                    mma_tf32(acc[mi][ni], afr[mi], bfr[ni]);
        }

        if (t + 1 < ktiles) {
            int nb = buf ^ 1;
            ((float4*)AsF[nb])[tid]       = avp[0];
            ((float4*)AsF[nb])[tid + 256] = avp[1];
            #pragma unroll
            for (int l = 0; l < NB4; l++) ((float4*)BsF[nb])[tid + l * 256] = bvp[l];
            __syncthreads();
        }
    }

    int qm = lane >> 2;
    int qk = lane & 3;
    #pragma unroll
    for (int mi = 0; mi < MFRAG; mi++) {
        int r = br * 128 + warp_m * WM + mi * 16 + qm;
        #pragma unroll
        for (int ni = 0; ni < NFRAG; ni++) {
            int c = bc * BN + warp_n * WN + ni * 8 + 2 * qk;
            float2 v0 = make_float2(acc[mi][ni][0], acc[mi][ni][1]);
            float2 v1 = make_float2(acc[mi][ni][2], acc[mi][ni][3]);
            if (bias) {
                float2 bb = *(const float2*)&bias[c];
                v0.x += bb.x; v0.y += bb.y;
                v1.x += bb.x; v1.y += bb.y;
            }
            *(float2*)&C[(size_t)r * ldc + c] = v0;
            *(float2*)&C[(size_t)(r + 8) * ldc + c] = v1;
        }
    }
}

// ------------------------------ host orchestration ---------------------------
extern "C" void kernel_launch(void* const* d_in, const int* in_sizes, int n_in,
                              void* d_out, int out_size)
{
    const float* x       = (const float*)d_in[0];
    const int*   eidx    = (const int*)  d_in[1];
    const float* sage_Wl = (const float*)d_in[2];
    const float* sage_bl = (const float*)d_in[3];
    const float* sage_Wr = (const float*)d_in[4];
    const float* gcn1_W  = (const float*)d_in[5];
    const float* gcn1_b  = (const float*)d_in[6];
    const float* gcn2_W  = (const float*)d_in[7];
    const float* gcn2_b  = (const float*)d_in[8];
    const float* fc1_W   = (const float*)d_in[9];
    const float* fc1_b   = (const float*)d_in[10];
    const float* fc2_W   = (const float*)d_in[11];
    const float* fc2_b   = (const float*)d_in[12];
    const float* out_W   = (const float*)d_in[13];
    const float* out_b   = (const float*)d_in[14];
    float* out = (float*)d_out;

    const int* src = eidx;
    const int* dst = eidx + EE;

    float *P, *A, *B, *C, *D, *E, *Xt, *Wt, *Ht, *OWt;
    cudaGetSymbolAddress((void**)&P, g_P);
    cudaGetSymbolAddress((void**)&A, g_A);
    cudaGetSymbolAddress((void**)&B, g_B);
    cudaGetSymbolAddress((void**)&C, g_C);
    cudaGetSymbolAddress((void**)&D, g_D);
    cudaGetSymbolAddress((void**)&E, g_E);
    cudaGetSymbolAddress((void**)&Xt, g_Xt);
    cudaGetSymbolAddress((void**)&Wt, g_Wt);
    cudaGetSymbolAddress((void**)&Ht, g_Ht);
    cudaGetSymbolAddress((void**)&OWt, g_OWt);

    const int TPB = 256;

    // CSR build + degree normalizations
    k_zero_cnt<<<(NN + TPB - 1) / TPB, TPB>>>();
    k_count<<<(EE + TPB - 1) / TPB, TPB>>>(dst);
    k_dinv<<<(NN + TPB - 1) / TPB, TPB>>>();
    k_scan<<<1, 1024>>>();
    k_fill<<<(EE + TPB - 1) / TPB, TPB>>>(src, dst);

    // pack operands of the big GEMMs
    k_packA<<<NN * NN / 4 / TPB, TPB>>>(x, Xt, NN, NN, NN);
    k_packB<<<NN * 512 / 4 / TPB, TPB>>>(sage_Wl, sage_Wr, 256, NN, 512, 256, 64, Wt);
    k_packB<<<128 * 16384 / 4 / TPB, TPB>>>(out_W, out_W, 16384, 128, 16384, 16384, 128, OWt);

    // P = x @ [Wl | Wr]  (4096 x 512 x 4096), tf32 mma.sync
    {
        dim3 grid(512 / 64, NN / 128);
        gemm_tf32p<64, 32, 32><<<grid, 256>>>(NN, 512, NN, Xt, Wt, P, 512, nullptr);
    }

    // SAGE (gather, fused combine) -> B
    k_sage_gather<<<NN * 64 / TPB, TPB>>>(sage_bl);

    // GCN1: hw -> C, gather+bias+relu -> A
    {
        dim3 grid(256 / 64, NN / 64);
        sgemm64<<<grid, 256>>>(NN, 256, 256, B, 256, gcn1_W, 256, C, 256, nullptr, 0);
    }
    k_gcn_gather<<<NN * 64 / TPB, TPB>>>(C, gcn1_b, A, 6);

    // GCN2: hw -> D, gather+bias+relu -> E
    {
        dim3 grid(128 / 64, NN / 64);
        sgemm64<<<grid, 256>>>(NN, 128, 256, A, 256, gcn2_W, 128, D, 128, nullptr, 0);
    }
    k_gcn_gather<<<NN * 32 / TPB, TPB>>>(D, gcn2_b, E, 5);

    // fc1 / fc2
    {
        dim3 grid(128 / 64, NN / 64);
        sgemm64<<<grid, 256>>>(NN, 128, 128, E, 128, fc1_W, 128, D, 128, fc1_b, 1);
        sgemm64<<<grid, 256>>>(NN, 128, 128, D, 128, fc2_W, 128, C, 128, fc2_b, 1);
    }

    // head GEMM (4096 x 16384 x 128)
    k_packA<<<NN * 128 / 4 / TPB, TPB>>>(C, Ht, NN, 128, 128);
    {
        dim3 grid(16384 / 128, NN / 128);
        gemm_tf32p<128, 64, 32><<<grid, 256>>>(NN, 16384, 128, Ht, OWt, out, 16384, out_b);
    }
}

// round 9
// speedup vs baseline: 2.5742x; 1.0411x over previous
#include <cuda_runtime.h>
#include <cuda_bf16.h>
#include <math.h>
#include <stdint.h>

#define NN 4096
#define EE 65536

// ------------------- scratch (static device globals; no allocs) -------------
__device__ float g_P[NN * 512];
__device__ float g_A[NN * 256];
__device__ float g_B[NN * 256];
__device__ float g_C[NN * 256];
__device__ float g_D[NN * 128];
__device__ float g_E[NN * 128];
__device__ int   g_cnt[NN];
__device__ float g_dinv[NN];
__device__ int   g_rowptr[NN + 1];
__device__ int   g_fill[NN];
__device__ int   g_adj[EE];
// packed (tf32-rounded, fragment-tile-major) operands
__device__ float g_Xt[NN * NN];
__device__ float g_Wt[NN * 512];
__device__ float g_Ht[NN * 128];
__device__ float g_OWt[128 * 16384];

__device__ __forceinline__ float rtf32(float f) {
    uint32_t r;
    asm("cvt.rna.tf32.f32 %0, %1;" : "=r"(r) : "f"(f));
    return __uint_as_float(r);
}

// ------------------------------- CSR build ----------------------------------
__global__ void k_zero_cnt() {
    int i = blockIdx.x * blockDim.x + threadIdx.x;
    if (i < NN) g_cnt[i] = 0;
}
__global__ void k_count(const int* __restrict__ dst) {
    int e = blockIdx.x * blockDim.x + threadIdx.x;
    if (e < EE) atomicAdd(&g_cnt[dst[e]], 1);
}
__global__ void k_dinv() {
    int i = blockIdx.x * blockDim.x + threadIdx.x;
    if (i < NN) g_dinv[i] = rsqrtf((float)(g_cnt[i] + 1));
}
// single block, 1024 threads, 4 counts each -> exclusive row pointers
__global__ void k_scan() {
    __shared__ int ts[1024];
    int t = threadIdx.x;
    int4 c = ((const int4*)g_cnt)[t];
    int s = c.x + c.y + c.z + c.w;
    ts[t] = s;
    __syncthreads();
    for (int off = 1; off < 1024; off <<= 1) {
        int x = (t >= off) ? ts[t - off] : 0;
        __syncthreads();
        ts[t] += x;
        __syncthreads();
    }
    int excl = ts[t] - s;
    int p0 = excl, p1 = excl + c.x, p2 = p1 + c.y, p3 = p2 + c.z;
    g_rowptr[4 * t + 0] = p0;  g_fill[4 * t + 0] = p0;
    g_rowptr[4 * t + 1] = p1;  g_fill[4 * t + 1] = p1;
    g_rowptr[4 * t + 2] = p2;  g_fill[4 * t + 2] = p2;
    g_rowptr[4 * t + 3] = p3;  g_fill[4 * t + 3] = p3;
    if (t == 1023) g_rowptr[NN] = ts[t];
}
__global__ void k_fill(const int* __restrict__ src, const int* __restrict__ dst) {
    int e = blockIdx.x * blockDim.x + threadIdx.x;
    if (e >= EE) return;
    int pos = atomicAdd(&g_fill[dst[e]], 1);
    g_adj[pos] = src[e];
}

// ---------------------- gather-based aggregations ----------------------------
__global__ void k_sage_gather(const float* __restrict__ bl) {
    int t = blockIdx.x * blockDim.x + threadIdx.x;
    if (t >= NN * 64) return;
    int v = t >> 6;
    int q = t & 63;
    int beg = g_rowptr[v], end = g_rowptr[v + 1];
    const float4* P4 = (const float4*)g_P;
    float4 acc = make_float4(0.f, 0.f, 0.f, 0.f);
    for (int i = beg; i < end; i++) {
        int s = g_adj[i];
        float4 p = P4[(size_t)s * 128 + q];
        acc.x += p.x; acc.y += p.y; acc.z += p.z; acc.w += p.w;
    }
    float inv = 1.0f / fmaxf((float)(end - beg), 1.0f);
    float4 b = ((const float4*)bl)[q];
    float4 pr = P4[(size_t)v * 128 + 64 + q];
    float4 r;
    r.x = fmaxf(acc.x * inv + b.x + pr.x, 0.f);
    r.y = fmaxf(acc.y * inv + b.y + pr.y, 0.f);
    r.z = fmaxf(acc.z * inv + b.z + pr.z, 0.f);
    r.w = fmaxf(acc.w * inv + b.w + pr.w, 0.f);
    ((float4*)g_B)[(size_t)v * 64 + q] = r;
}

__global__ void k_gcn_gather(const float* __restrict__ hw, const float* __restrict__ bias,
                             float* __restrict__ out, int hqsh) {
    int t = blockIdx.x * blockDim.x + threadIdx.x;
    if (t >= (NN << hqsh)) return;
    int v = t >> hqsh;
    int q = t & ((1 << hqsh) - 1);
    int Hq = 1 << hqsh;
    int beg = g_rowptr[v], end = g_rowptr[v + 1];
    float dv = g_dinv[v];
    const float4* H4 = (const float4*)hw;
    float4 self = H4[(size_t)v * Hq + q];
    float dv2 = dv * dv;
    float4 acc = make_float4(dv2 * self.x, dv2 * self.y, dv2 * self.z, dv2 * self.w);
    for (int i = beg; i < end; i++) {
        int s = g_adj[i];
        float nm = dv * g_dinv[s];
        float4 p = H4[(size_t)s * Hq + q];
        acc.x += nm * p.x; acc.y += nm * p.y; acc.z += nm * p.z; acc.w += nm * p.w;
    }
    float4 b = ((const float4*)bias)[q];
    float4 r;
    r.x = fmaxf(acc.x + b.x, 0.f);
    r.y = fmaxf(acc.y + b.y, 0.f);
    r.z = fmaxf(acc.z + b.z, 0.f);
    r.w = fmaxf(acc.w + b.w, 0.f);
    ((float4*)out)[(size_t)v * Hq + q] = r;
}

// ---- pack A operand: round to tf32 + permute to fragment-tile-major --------
__global__ void k_packA(const float* __restrict__ in, float* __restrict__ out,
                        int M, int K, int lda) {
    int o = blockIdx.x * blockDim.x + threadIdx.x;
    int total = (M * K) >> 2;
    if (o >= total) return;
    int perBlk = (K >> 4) << 9;
    int br = o / perBlk;
    int r = o - br * perBlk;
    int t = r >> 9;
    int q = r & 511;
    int s = q >> 8;
    int t8 = (q >> 5) & 7;
    int lane = q & 31;
    int m = br * 128 + t8 * 16 + (lane >> 2);
    int k = t * 16 + s * 8 + (lane & 3);
    const float* base = in + (size_t)m * lda + k;
    float4 v;
    v.x = rtf32(base[0]);
    v.y = rtf32(base[(size_t)8 * lda]);
    v.z = rtf32(base[4]);
    v.w = rtf32(base[(size_t)8 * lda + 4]);
    ((float4*)out)[o] = v;
}

// ---- pack B operand, PAIRED n-fragments ------------------------------------
__global__ void k_packB(const float* __restrict__ B0, const float* __restrict__ B1,
                        int nsplit, int K, int N, int ldb, int BN,
                        float* __restrict__ out) {
    int o = blockIdx.x * blockDim.x + threadIdx.x;
    int total = (K * N) >> 2;
    if (o >= total) return;
    int perBc = (K * BN) >> 2;
    int bc = o / perBc;
    int r = o - bc * perBc;
    int perTile = BN * 4;
    int t = r / perTile;
    int q = r - t * perTile;
    int s = q / (BN * 2);
    int q2 = q - s * (BN * 2);
    int u2 = q2 >> 5;
    int lane = q2 & 31;
    int k = t * 16 + s * 8 + (lane & 3);
    int n = bc * BN + u2 * 16 + (lane >> 2);
    const float* src = B0;
    if (n >= nsplit) { src = B1; n -= nsplit; }
    float4 v;
    v.x = rtf32(src[(size_t)k * ldb + n]);
    v.y = rtf32(src[(size_t)(k + 4) * ldb + n]);
    v.z = rtf32(src[(size_t)k * ldb + n + 8]);
    v.w = rtf32(src[(size_t)(k + 4) * ldb + n + 8]);
    ((float4*)out)[o] = v;
}

// ------------------- fp32 SIMT GEMM, 64x64x16 tiles (small layers) ----------
__global__ void __launch_bounds__(256, 4)
sgemm64(int M, int N, int K,
        const float* __restrict__ A, int lda,
        const float* __restrict__ B, int ldb,
        float* __restrict__ C, int ldc,
        const float* __restrict__ bias, int do_relu)
{
    const int BK = 16;
    __shared__ float As[2][BK][64];
    __shared__ float Bs[2][BK][64];

    int tid = threadIdx.x;
    int tx = tid & 15;
    int ty = tid >> 4;
    int row0 = blockIdx.y * 64;
    int col0 = blockIdx.x * 64;

    int am = tid >> 2;
    int ak = (tid & 3) << 2;
    int bk = tid >> 4;
    int bn = (tid & 15) << 2;

    const float* Aptr = A + (size_t)(row0 + am) * lda + ak;
    const float* Bptr = B + (size_t)bk * ldb + col0 + bn;
    size_t bstep = (size_t)BK * ldb;

    float4 av = *(const float4*)Aptr;
    float4 bv = *(const float4*)Bptr;
    As[0][ak + 0][am] = av.x;
    As[0][ak + 1][am] = av.y;
    As[0][ak + 2][am] = av.z;
    As[0][ak + 3][am] = av.w;
    *(float4*)&Bs[0][bk][bn] = bv;
    __syncthreads();

    float acc[4][4];
    #pragma unroll
    for (int i = 0; i < 4; i++)
        #pragma unroll
        for (int j = 0; j < 4; j++) acc[i][j] = 0.0f;

    int ntiles = K / BK;
    for (int t = 0; t < ntiles; t++) {
        int buf = t & 1;
        if (t + 1 < ntiles) {
            av = *(const float4*)(Aptr + (size_t)(t + 1) * BK);
            bv = *(const float4*)(Bptr + (size_t)(t + 1) * bstep);
        }
        #pragma unroll
        for (int k = 0; k < BK; k++) {
            float a[4], b[4];
            *(float4*)&a[0] = *(float4*)&As[buf][k][ty * 4];
            *(float4*)&b[0] = *(float4*)&Bs[buf][k][tx * 4];
            #pragma unroll
            for (int i = 0; i < 4; i++)
                #pragma unroll
                for (int j = 0; j < 4; j++)
                    acc[i][j] = fmaf(a[i], b[j], acc[i][j]);
        }
        if (t + 1 < ntiles) {
            int nb = buf ^ 1;
            As[nb][ak + 0][am] = av.x;
            As[nb][ak + 1][am] = av.y;
            As[nb][ak + 2][am] = av.z;
            As[nb][ak + 3][am] = av.w;
            *(float4*)&Bs[nb][bk][bn] = bv;
            __syncthreads();
        }
    }

    #pragma unroll
    for (int i = 0; i < 4; i++) {
        int gm = row0 + ty * 4 + i;
        int gn = col0 + tx * 4;
        float4 v = make_float4(acc[i][0], acc[i][1], acc[i][2], acc[i][3]);
        if (bias) {
            v.x += bias[gn + 0];
            v.y += bias[gn + 1];
            v.z += bias[gn + 2];
            v.w += bias[gn + 3];
        }
        if (do_relu) {
            v.x = fmaxf(v.x, 0.0f);
            v.y = fmaxf(v.y, 0.0f);
            v.z = fmaxf(v.z, 0.0f);
            v.w = fmaxf(v.w, 0.0f);
        }
        *(float4*)&C[(size_t)gm * ldc + gn] = v;
    }
}

// ------------- mma.sync tf32 GEMM on pre-packed operands --------------------
__device__ __forceinline__ void mma_tf32(float* c, const uint32_t* a, const uint32_t* b) {
    asm volatile(
        "mma.sync.aligned.m16n8k8.row.col.f32.tf32.tf32.f32 "
        "{%0,%1,%2,%3}, {%4,%5,%6,%7}, {%8,%9}, {%0,%1,%2,%3};"
        : "+f"(c[0]), "+f"(c[1]), "+f"(c[2]), "+f"(c[3])
        : "r"(a[0]), "r"(a[1]), "r"(a[2]), "r"(a[3]), "r"(b[0]), "r"(b[1]));
}

template<int BN, int WM, int WN>
__global__ void __launch_bounds__(256, 2)
gemm_tf32p(int M, int N, int K,
           const float* __restrict__ At,
           const float* __restrict__ Bt,
           float* __restrict__ C, int ldc,
           const float* __restrict__ bias)
{
    const int MFRAG = WM / 16;
    const int NFRAG = WN / 8;
    const int WARPS_N = BN / WN;
    const int ATILE = 2048;
    const int BTILE = 16 * BN;
    const int NB4 = BTILE / 4 / 256;

    __shared__ float AsF[2][ATILE];
    __shared__ float BsF[2][BTILE];

    int tid = threadIdx.x;
    int lane = tid & 31;
    int warp = tid >> 5;
    int warp_m = warp / WARPS_N;
    int warp_n = warp % WARPS_N;

    int br = blockIdx.y;
    int bc = blockIdx.x;
    int ktiles = K >> 4;

    const float4* Ab = (const float4*)(At + (size_t)br * ktiles * ATILE);
    const float4* Bb = (const float4*)(Bt + (size_t)bc * ktiles * BTILE);

    float4 avp[2], bvp[2];
    avp[0] = Ab[tid];
    avp[1] = Ab[tid + 256];
    #pragma unroll
    for (int l = 0; l < NB4; l++) bvp[l] = Bb[tid + l * 256];

    ((float4*)AsF[0])[tid]       = avp[0];
    ((float4*)AsF[0])[tid + 256] = avp[1];
    #pragma unroll
    for (int l = 0; l < NB4; l++) ((float4*)BsF[0])[tid + l * 256] = bvp[l];
    __syncthreads();

    float acc[MFRAG][NFRAG][4];
    #pragma unroll
    for (int mi = 0; mi < MFRAG; mi++)
        #pragma unroll
        for (int ni = 0; ni < NFRAG; ni++)
            #pragma unroll
            for (int j = 0; j < 4; j++) acc[mi][ni][j] = 0.0f;

    for (int t = 0; t < ktiles; t++) {
        int buf = t & 1;
        if (t + 1 < ktiles) {
            const float4* An = Ab + (size_t)(t + 1) * (ATILE / 4);
            const float4* Bn = Bb + (size_t)(t + 1) * (BTILE / 4);
            avp[0] = An[tid];
            avp[1] = An[tid + 256];
            #pragma unroll
            for (int l = 0; l < NB4; l++) bvp[l] = Bn[tid + l * 256];
        }

        #pragma unroll
        for (int s = 0; s < 2; s++) {
            uint32_t afr[MFRAG][4];
            uint32_t bfr[NFRAG][2];
            #pragma unroll
            for (int mi = 0; mi < MFRAG; mi++) {
                int t8 = warp_m * MFRAG + mi;
                float4 fa = *(const float4*)&AsF[buf][(((s << 3) + t8) * 32 + lane) * 4];
                afr[mi][0] = __float_as_uint(fa.x);
                afr[mi][1] = __float_as_uint(fa.y);
                afr[mi][2] = __float_as_uint(fa.z);
                afr[mi][3] = __float_as_uint(fa.w);
            }
            // paired B fragments: one LDS.128 covers two n-tiles
            #pragma unroll
            for (int ni2 = 0; ni2 < NFRAG / 2; ni2++) {
                int u2 = warp_n * (WN / 16) + ni2;
                float4 fb = *(const float4*)&BsF[buf][((s * (BN / 16) + u2) * 32 + lane) * 4];
                bfr[2 * ni2][0]     = __float_as_uint(fb.x);
                bfr[2 * ni2][1]     = __float_as_uint(fb.y);
                bfr[2 * ni2 + 1][0] = __float_as_uint(fb.z);
                bfr[2 * ni2 + 1][1] = __float_as_uint(fb.w);
            }
            #pragma unroll
            for (int mi = 0; mi < MFRAG; mi++)
                #pragma unroll
                for (int ni = 0; ni < NFRAG; ni++)
                    mma_tf32(acc[mi][ni], afr[mi], bfr[ni]);
        }

        if (t + 1 < ktiles) {
            int nb = buf ^ 1;
            ((float4*)AsF[nb])[tid]       = avp[0];
            ((float4*)AsF[nb])[tid + 256] = avp[1];
            #pragma unroll
            for (int l = 0; l < NB4; l++) ((float4*)BsF[nb])[tid + l * 256] = bvp[l];
            __syncthreads();
        }
    }

    int qm = lane >> 2;
    int qk = lane & 3;
    #pragma unroll
    for (int mi = 0; mi < MFRAG; mi++) {
        int r = br * 128 + warp_m * WM + mi * 16 + qm;
        #pragma unroll
        for (int ni = 0; ni < NFRAG; ni++) {
            int c = bc * BN + warp_n * WN + ni * 8 + 2 * qk;
            float2 v0 = make_float2(acc[mi][ni][0], acc[mi][ni][1]);
            float2 v1 = make_float2(acc[mi][ni][2], acc[mi][ni][3]);
            if (bias) {
                float2 bb = *(const float2*)&bias[c];
                v0.x += bb.x; v0.y += bb.y;
                v1.x += bb.x; v1.y += bb.y;
            }
            *(float2*)&C[(size_t)r * ldc + c] = v0;
            *(float2*)&C[(size_t)(r + 8) * ldc + c] = v1;
        }
    }
}

// ------------------------------ host orchestration ---------------------------
extern "C" void kernel_launch(void* const* d_in, const int* in_sizes, int n_in,
                              void* d_out, int out_size)
{
    const float* x       = (const float*)d_in[0];
    const int*   eidx    = (const int*)  d_in[1];
    const float* sage_Wl = (const float*)d_in[2];
    const float* sage_bl = (const float*)d_in[3];
    const float* sage_Wr = (const float*)d_in[4];
    const float* gcn1_W  = (const float*)d_in[5];
    const float* gcn1_b  = (const float*)d_in[6];
    const float* gcn2_W  = (const float*)d_in[7];
    const float* gcn2_b  = (const float*)d_in[8];
    const float* fc1_W   = (const float*)d_in[9];
    const float* fc1_b   = (const float*)d_in[10];
    const float* fc2_W   = (const float*)d_in[11];
    const float* fc2_b   = (const float*)d_in[12];
    const float* out_W   = (const float*)d_in[13];
    const float* out_b   = (const float*)d_in[14];
    float* out = (float*)d_out;

    const int* src = eidx;
    const int* dst = eidx + EE;

    float *P, *A, *B, *C, *D, *E, *Xt, *Wt, *Ht, *OWt;
    cudaGetSymbolAddress((void**)&P, g_P);
    cudaGetSymbolAddress((void**)&A, g_A);
    cudaGetSymbolAddress((void**)&B, g_B);
    cudaGetSymbolAddress((void**)&C, g_C);
    cudaGetSymbolAddress((void**)&D, g_D);
    cudaGetSymbolAddress((void**)&E, g_E);
    cudaGetSymbolAddress((void**)&Xt, g_Xt);
    cudaGetSymbolAddress((void**)&Wt, g_Wt);
    cudaGetSymbolAddress((void**)&Ht, g_Ht);
    cudaGetSymbolAddress((void**)&OWt, g_OWt);

    const int TPB = 256;

    // CSR build + degree normalizations
    k_zero_cnt<<<(NN + TPB - 1) / TPB, TPB>>>();
    k_count<<<(EE + TPB - 1) / TPB, TPB>>>(dst);
    k_dinv<<<(NN + TPB - 1) / TPB, TPB>>>();
    k_scan<<<1, 1024>>>();
    k_fill<<<(EE + TPB - 1) / TPB, TPB>>>(src, dst);

    // pack operands of the big GEMMs (both B packs now BN=128)
    k_packA<<<NN * NN / 4 / TPB, TPB>>>(x, Xt, NN, NN, NN);
    k_packB<<<NN * 512 / 4 / TPB, TPB>>>(sage_Wl, sage_Wr, 256, NN, 512, 256, 128, Wt);
    k_packB<<<128 * 16384 / 4 / TPB, TPB>>>(out_W, out_W, 16384, 128, 16384, 16384, 128, OWt);

    // P = x @ [Wl | Wr]  (4096 x 512 x 4096), BN=128 -> grid 4x32
    {
        dim3 grid(512 / 128, NN / 128);
        gemm_tf32p<128, 64, 32><<<grid, 256>>>(NN, 512, NN, Xt, Wt, P, 512, nullptr);
    }

    // SAGE (gather, fused combine) -> B
    k_sage_gather<<<NN * 64 / TPB, TPB>>>(sage_bl);

    // GCN1: hw -> C, gather+bias+relu -> A
    {
        dim3 grid(256 / 64, NN / 64);
        sgemm64<<<grid, 256>>>(NN, 256, 256, B, 256, gcn1_W, 256, C, 256, nullptr, 0);
    }
    k_gcn_gather<<<NN * 64 / TPB, TPB>>>(C, gcn1_b, A, 6);

    // GCN2: hw -> D, gather+bias+relu -> E
    {
        dim3 grid(128 / 64, NN / 64);
        sgemm64<<<grid, 256>>>(NN, 128, 256, A, 256, gcn2_W, 128, D, 128, nullptr, 0);
    }
    k_gcn_gather<<<NN * 32 / TPB, TPB>>>(D, gcn2_b, E, 5);

    // fc1 / fc2
    {
        dim3 grid(128 / 64, NN / 64);
        sgemm64<<<grid, 256>>>(NN, 128, 128, E, 128, fc1_W, 128, D, 128, fc1_b, 1);
        sgemm64<<<grid, 256>>>(NN, 128, 128, D, 128, fc2_W, 128, C, 128, fc2_b, 1);
    }

    // head GEMM (4096 x 16384 x 128)
    k_packA<<<NN * 128 / 4 / TPB, TPB>>>(C, Ht, NN, 128, 128);
    {
        dim3 grid(16384 / 128, NN / 128);
        gemm_tf32p<128, 64, 32><<<grid, 256>>>(NN, 16384, 128, Ht, OWt, out, 16384, out_b);
    }
}

// round 10
// speedup vs baseline: 2.9365x; 1.1407x over previous
#include <cuda_runtime.h>
#include <cuda_bf16.h>
#include <math.h>
#include <stdint.h>

#define NN 4096
#define EE 65536

// ------------------- scratch (static device globals; no allocs) -------------
__device__ float g_P[NN * 1024];   // split-K=2: two 4096x512 partials
__device__ float g_A[NN * 256];
__device__ float g_B[NN * 256];
__device__ float g_C[NN * 256];
__device__ float g_D[NN * 128];
__device__ float g_E[NN * 128];
__device__ float g_dinv[NN];
__device__ int   g_rowptr[NN + 1];
__device__ int   g_fill[NN];
__device__ int   g_adj[EE];
// packed (tf32-rounded, fragment-tile-major) operands
__device__ float g_Xt[NN * NN];
__device__ float g_Wt[NN * 512];
__device__ float g_Ht[NN * 128];
__device__ float g_OWt[128 * 16384];

__device__ __forceinline__ float rtf32(float f) {
    uint32_t r;
    asm("cvt.rna.tf32.f32 %0, %1;" : "=r"(r) : "f"(f));
    return __uint_as_float(r);
}

// --------------------- fused CSR build (1 block, 1024 thr) ------------------
__global__ void k_csr(const int* __restrict__ dst) {
    __shared__ int sc[NN];
    __shared__ int ts[1024];
    int t = threadIdx.x;
    ((int4*)sc)[t] = make_int4(0, 0, 0, 0);
    __syncthreads();
    for (int e = t; e < EE; e += 1024) atomicAdd(&sc[dst[e]], 1);
    __syncthreads();
    int4 c = ((int4*)sc)[t];
    int s = c.x + c.y + c.z + c.w;
    ts[t] = s;
    __syncthreads();
    for (int off = 1; off < 1024; off <<= 1) {
        int x = (t >= off) ? ts[t - off] : 0;
        __syncthreads();
        ts[t] += x;
        __syncthreads();
    }
    int excl = ts[t] - s;
    int p0 = excl, p1 = excl + c.x, p2 = p1 + c.y, p3 = p2 + c.z;
    g_rowptr[4 * t + 0] = p0;  g_fill[4 * t + 0] = p0;
    g_rowptr[4 * t + 1] = p1;  g_fill[4 * t + 1] = p1;
    g_rowptr[4 * t + 2] = p2;  g_fill[4 * t + 2] = p2;
    g_rowptr[4 * t + 3] = p3;  g_fill[4 * t + 3] = p3;
    g_dinv[4 * t + 0] = rsqrtf((float)(c.x + 1));
    g_dinv[4 * t + 1] = rsqrtf((float)(c.y + 1));
    g_dinv[4 * t + 2] = rsqrtf((float)(c.z + 1));
    g_dinv[4 * t + 3] = rsqrtf((float)(c.w + 1));
    if (t == 1023) g_rowptr[NN] = ts[t];
}
__global__ void k_fill(const int* __restrict__ src, const int* __restrict__ dst) {
    int e = blockIdx.x * blockDim.x + threadIdx.x;
    if (e >= EE) return;
    int pos = atomicAdd(&g_fill[dst[e]], 1);
    g_adj[pos] = src[e];
}

// ---------------------- gather-based aggregations ----------------------------
// SAGE with fused split-K sum: P = P0 + P1 (two partial buffers)
__global__ void k_sage_gather(const float* __restrict__ bl) {
    int t = blockIdx.x * blockDim.x + threadIdx.x;
    if (t >= NN * 64) return;
    int v = t >> 6;
    int q = t & 63;
    int beg = g_rowptr[v], end = g_rowptr[v + 1];
    const float4* P4 = (const float4*)g_P;
    const float4* Q4 = P4 + NN * 128;     // second K-half partial
    float4 acc = make_float4(0.f, 0.f, 0.f, 0.f);
    for (int i = beg; i < end; i++) {
        int s = g_adj[i];
        float4 p = P4[(size_t)s * 128 + q];
        float4 p2 = Q4[(size_t)s * 128 + q];
        acc.x += p.x + p2.x; acc.y += p.y + p2.y;
        acc.z += p.z + p2.z; acc.w += p.w + p2.w;
    }
    float inv = 1.0f / fmaxf((float)(end - beg), 1.0f);
    float4 b = ((const float4*)bl)[q];
    float4 pr = P4[(size_t)v * 128 + 64 + q];
    float4 pr2 = Q4[(size_t)v * 128 + 64 + q];
    float4 r;
    r.x = fmaxf(acc.x * inv + b.x + pr.x + pr2.x, 0.f);
    r.y = fmaxf(acc.y * inv + b.y + pr.y + pr2.y, 0.f);
    r.z = fmaxf(acc.z * inv + b.z + pr.z + pr2.z, 0.f);
    r.w = fmaxf(acc.w * inv + b.w + pr.w + pr2.w, 0.f);
    ((float4*)g_B)[(size_t)v * 64 + q] = r;
}

__global__ void k_gcn_gather(const float* __restrict__ hw, const float* __restrict__ bias,
                             float* __restrict__ out, int hqsh) {
    int t = blockIdx.x * blockDim.x + threadIdx.x;
    if (t >= (NN << hqsh)) return;
    int v = t >> hqsh;
    int q = t & ((1 << hqsh) - 1);
    int Hq = 1 << hqsh;
    int beg = g_rowptr[v], end = g_rowptr[v + 1];
    float dv = g_dinv[v];
    const float4* H4 = (const float4*)hw;
    float4 self = H4[(size_t)v * Hq + q];
    float dv2 = dv * dv;
    float4 acc = make_float4(dv2 * self.x, dv2 * self.y, dv2 * self.z, dv2 * self.w);
    for (int i = beg; i < end; i++) {
        int s = g_adj[i];
        float nm = dv * g_dinv[s];
        float4 p = H4[(size_t)s * Hq + q];
        acc.x += nm * p.x; acc.y += nm * p.y; acc.z += nm * p.z; acc.w += nm * p.w;
    }
    float4 b = ((const float4*)bias)[q];
    float4 r;
    r.x = fmaxf(acc.x + b.x, 0.f);
    r.y = fmaxf(acc.y + b.y, 0.f);
    r.z = fmaxf(acc.z + b.z, 0.f);
    r.w = fmaxf(acc.w + b.w, 0.f);
    ((float4*)out)[(size_t)v * Hq + q] = r;
}

// ---- pack A operand: round to tf32 + permute to fragment-tile-major --------
__global__ void k_packA(const float* __restrict__ in, float* __restrict__ out,
                        int M, int K, int lda) {
    int o = blockIdx.x * blockDim.x + threadIdx.x;
    int total = (M * K) >> 2;
    if (o >= total) return;
    int perBlk = (K >> 4) << 9;
    int br = o / perBlk;
    int r = o - br * perBlk;
    int t = r >> 9;
    int q = r & 511;
    int s = q >> 8;
    int t8 = (q >> 5) & 7;
    int lane = q & 31;
    int m = br * 128 + t8 * 16 + (lane >> 2);
    int k = t * 16 + s * 8 + (lane & 3);
    const float* base = in + (size_t)m * lda + k;
    float4 v;
    v.x = rtf32(base[0]);
    v.y = rtf32(base[(size_t)8 * lda]);
    v.z = rtf32(base[4]);
    v.w = rtf32(base[(size_t)8 * lda + 4]);
    ((float4*)out)[o] = v;
}

// ---- pack B operand, PAIRED n-fragments ------------------------------------
__global__ void k_packB(const float* __restrict__ B0, const float* __restrict__ B1,
                        int nsplit, int K, int N, int ldb, int BN,
                        float* __restrict__ out) {
    int o = blockIdx.x * blockDim.x + threadIdx.x;
    int total = (K * N) >> 2;
    if (o >= total) return;
    int perBc = (K * BN) >> 2;
    int bc = o / perBc;
    int r = o - bc * perBc;
    int perTile = BN * 4;
    int t = r / perTile;
    int q = r - t * perTile;
    int s = q / (BN * 2);
    int q2 = q - s * (BN * 2);
    int u2 = q2 >> 5;
    int lane = q2 & 31;
    int k = t * 16 + s * 8 + (lane & 3);
    int n = bc * BN + u2 * 16 + (lane >> 2);
    const float* src = B0;
    if (n >= nsplit) { src = B1; n -= nsplit; }
    float4 v;
    v.x = rtf32(src[(size_t)k * ldb + n]);
    v.y = rtf32(src[(size_t)(k + 4) * ldb + n]);
    v.z = rtf32(src[(size_t)k * ldb + n + 8]);
    v.w = rtf32(src[(size_t)(k + 4) * ldb + n + 8]);
    ((float4*)out)[o] = v;
}

// ------------------- fp32 SIMT GEMM, 64x64x16 tiles (GCN layers) ------------
__global__ void __launch_bounds__(256, 4)
sgemm64(int M, int N, int K,
        const float* __restrict__ A, int lda,
        const float* __restrict__ B, int ldb,
        float* __restrict__ C, int ldc)
{
    const int BK = 16;
    __shared__ float As[2][BK][64];
    __shared__ float Bs[2][BK][64];

    int tid = threadIdx.x;
    int tx = tid & 15;
    int ty = tid >> 4;
    int row0 = blockIdx.y * 64;
    int col0 = blockIdx.x * 64;

    int am = tid >> 2;
    int ak = (tid & 3) << 2;
    int bk = tid >> 4;
    int bn = (tid & 15) << 2;

    const float* Aptr = A + (size_t)(row0 + am) * lda + ak;
    const float* Bptr = B + (size_t)bk * ldb + col0 + bn;
    size_t bstep = (size_t)BK * ldb;

    float4 av = *(const float4*)Aptr;
    float4 bv = *(const float4*)Bptr;
    As[0][ak + 0][am] = av.x;
    As[0][ak + 1][am] = av.y;
    As[0][ak + 2][am] = av.z;
    As[0][ak + 3][am] = av.w;
    *(float4*)&Bs[0][bk][bn] = bv;
    __syncthreads();

    float acc[4][4];
    #pragma unroll
    for (int i = 0; i < 4; i++)
        #pragma unroll
        for (int j = 0; j < 4; j++) acc[i][j] = 0.0f;

    int ntiles = K / BK;
    for (int t = 0; t < ntiles; t++) {
        int buf = t & 1;
        if (t + 1 < ntiles) {
            av = *(const float4*)(Aptr + (size_t)(t + 1) * BK);
            bv = *(const float4*)(Bptr + (size_t)(t + 1) * bstep);
        }
        #pragma unroll
        for (int k = 0; k < BK; k++) {
            float a[4], b[4];
            *(float4*)&a[0] = *(float4*)&As[buf][k][ty * 4];
            *(float4*)&b[0] = *(float4*)&Bs[buf][k][tx * 4];
            #pragma unroll
            for (int i = 0; i < 4; i++)
                #pragma unroll
                for (int j = 0; j < 4; j++)
                    acc[i][j] = fmaf(a[i], b[j], acc[i][j]);
        }
        if (t + 1 < ntiles) {
            int nb = buf ^ 1;
            As[nb][ak + 0][am] = av.x;
            As[nb][ak + 1][am] = av.y;
            As[nb][ak + 2][am] = av.z;
            As[nb][ak + 3][am] = av.w;
            *(float4*)&Bs[nb][bk][bn] = bv;
            __syncthreads();
        }
    }

    #pragma unroll
    for (int i = 0; i < 4; i++) {
        int gm = row0 + ty * 4 + i;
        int gn = col0 + tx * 4;
        *(float4*)&C[(size_t)gm * ldc + gn] =
            make_float4(acc[i][0], acc[i][1], acc[i][2], acc[i][3]);
    }
}

// ---------------- fused fc1+fc2: C = relu(relu(D@W1+b1)@W2+b2) --------------
// CTA: 64 rows x full 128 cols. Single-buffered smem (<48KB static limit).
__global__ void __launch_bounds__(256, 2)
k_fc12(const float* __restrict__ D,
       const float* __restrict__ W1, const float* __restrict__ b1,
       const float* __restrict__ W2, const float* __restrict__ b2,
       float* __restrict__ C)
{
    __shared__ float As[16][64];
    __shared__ float Bs[16][128];
    __shared__ float hs[64][132];

    int tid = threadIdx.x;
    int tx = tid & 15;
    int ty = tid >> 4;
    int row0 = blockIdx.x * 64;
    int am = tid >> 2;
    int ak = (tid & 3) << 2;

    float acc[4][8];
    #pragma unroll
    for (int i = 0; i < 4; i++)
        #pragma unroll
        for (int j = 0; j < 8; j++) acc[i][j] = 0.0f;

    // phase 1: h = relu(D[64x128] @ W1[128x128] + b1)
    for (int t = 0; t < 8; t++) {
        __syncthreads();
        {
            float4 av = *(const float4*)&D[(size_t)(row0 + am) * 128 + t * 16 + ak];
            As[ak + 0][am] = av.x;
            As[ak + 1][am] = av.y;
            As[ak + 2][am] = av.z;
            As[ak + 3][am] = av.w;
            #pragma unroll
            for (int l = 0; l < 2; l++) {
                int i = tid + l * 256;
                int bk = i >> 5;
                int bn = (i & 31) << 2;
                *(float4*)&Bs[bk][bn] = *(const float4*)&W1[(size_t)(t * 16 + bk) * 128 + bn];
            }
        }
        __syncthreads();
        #pragma unroll
        for (int k = 0; k < 16; k++) {
            float a[4], b[8];
            *(float4*)&a[0] = *(float4*)&As[k][ty * 4];
            *(float4*)&b[0] = *(float4*)&Bs[k][tx * 8];
            *(float4*)&b[4] = *(float4*)&Bs[k][tx * 8 + 4];
            #pragma unroll
            for (int i = 0; i < 4; i++)
                #pragma unroll
                for (int j = 0; j < 8; j++)
                    acc[i][j] = fmaf(a[i], b[j], acc[i][j]);
        }
    }
    __syncthreads();
    #pragma unroll
    for (int i = 0; i < 4; i++)
        #pragma unroll
        for (int j = 0; j < 8; j++)
            hs[ty * 4 + i][tx * 8 + j] = fmaxf(acc[i][j] + b1[tx * 8 + j], 0.0f);

    // phase 2: C = relu(h @ W2[128x128] + b2)
    #pragma unroll
    for (int i = 0; i < 4; i++)
        #pragma unroll
        for (int j = 0; j < 8; j++) acc[i][j] = 0.0f;

    for (int t = 0; t < 8; t++) {
        __syncthreads();
        #pragma unroll
        for (int l = 0; l < 2; l++) {
            int i = tid + l * 256;
            int bk = i >> 5;
            int bn = (i & 31) << 2;
            *(float4*)&Bs[bk][bn] = *(const float4*)&W2[(size_t)(t * 16 + bk) * 128 + bn];
        }
        __syncthreads();
        #pragma unroll
        for (int k = 0; k < 16; k++) {
            int kk = t * 16 + k;
            float b[8];
            *(float4*)&b[0] = *(float4*)&Bs[k][tx * 8];
            *(float4*)&b[4] = *(float4*)&Bs[k][tx * 8 + 4];
            #pragma unroll
            for (int i = 0; i < 4; i++) {
                float a = hs[ty * 4 + i][kk];
                #pragma unroll
                for (int j = 0; j < 8; j++)
                    acc[i][j] = fmaf(a, b[j], acc[i][j]);
            }
        }
    }
    #pragma unroll
    for (int i = 0; i < 4; i++) {
        int gm = row0 + ty * 4 + i;
        #pragma unroll
        for (int j = 0; j < 8; j += 4) {
            int gn = tx * 8 + j;
            float4 v;
            v.x = fmaxf(acc[i][j + 0] + b2[gn + 0], 0.f);
            v.y = fmaxf(acc[i][j + 1] + b2[gn + 1], 0.f);
            v.z = fmaxf(acc[i][j + 2] + b2[gn + 2], 0.f);
            v.w = fmaxf(acc[i][j + 3] + b2[gn + 3], 0.f);
            *(float4*)&C[(size_t)gm * 128 + gn] = v;
        }
    }
}

// ------------- mma.sync tf32 GEMM on pre-packed operands --------------------
// Supports split-K via gridDim.z: z-slice consumes ktiles starting at
// z*ktiles within each row/col block (block stride = ktstride tiles),
// writing to C + z*czstride.
__device__ __forceinline__ void mma_tf32(float* c, const uint32_t* a, const uint32_t* b) {
    asm volatile(
        "mma.sync.aligned.m16n8k8.row.col.f32.tf32.tf32.f32 "
        "{%0,%1,%2,%3}, {%4,%5,%6,%7}, {%8,%9}, {%0,%1,%2,%3};"
        : "+f"(c[0]), "+f"(c[1]), "+f"(c[2]), "+f"(c[3])
        : "r"(a[0]), "r"(a[1]), "r"(a[2]), "r"(a[3]), "r"(b[0]), "r"(b[1]));
}

template<int BN, int WM, int WN>
__global__ void __launch_bounds__(256, 2)
gemm_tf32p(int ktiles, int ktstride, size_t czstride,
           const float* __restrict__ At,
           const float* __restrict__ Bt,
           float* __restrict__ C, int ldc,
           const float* __restrict__ bias)
{
    const int MFRAG = WM / 16;
    const int NFRAG = WN / 8;
    const int WARPS_N = BN / WN;
    const int ATILE = 2048;
    const int BTILE = 16 * BN;
    const int NB4 = BTILE / 4 / 256;

    __shared__ float AsF[2][ATILE];
    __shared__ float BsF[2][BTILE];

    int tid = threadIdx.x;
    int lane = tid & 31;
    int warp = tid >> 5;
    int warp_m = warp / WARPS_N;
    int warp_n = warp % WARPS_N;

    int br = blockIdx.y;
    int bc = blockIdx.x;
    int kt0 = blockIdx.z * ktiles;

    const float4* Ab = (const float4*)At + ((size_t)br * ktstride + kt0) * (ATILE / 4);
    const float4* Bb = (const float4*)Bt + ((size_t)bc * ktstride + kt0) * (BTILE / 4);
    C += (size_t)blockIdx.z * czstride;

    float4 avp[2], bvp[2];
    avp[0] = Ab[tid];
    avp[1] = Ab[tid + 256];
    #pragma unroll
    for (int l = 0; l < NB4; l++) bvp[l] = Bb[tid + l * 256];

    ((float4*)AsF[0])[tid]       = avp[0];
    ((float4*)AsF[0])[tid + 256] = avp[1];
    #pragma unroll
    for (int l = 0; l < NB4; l++) ((float4*)BsF[0])[tid + l * 256] = bvp[l];
    __syncthreads();

    float acc[MFRAG][NFRAG][4];
    #pragma unroll
    for (int mi = 0; mi < MFRAG; mi++)
        #pragma unroll
        for (int ni = 0; ni < NFRAG; ni++)
            #pragma unroll
            for (int j = 0; j < 4; j++) acc[mi][ni][j] = 0.0f;

    for (int t = 0; t < ktiles; t++) {
        int buf = t & 1;
        if (t + 1 < ktiles) {
            const float4* An = Ab + (size_t)(t + 1) * (ATILE / 4);
            const float4* Bn = Bb + (size_t)(t + 1) * (BTILE / 4);
            avp[0] = An[tid];
            avp[1] = An[tid + 256];
            #pragma unroll
            for (int l = 0; l < NB4; l++) bvp[l] = Bn[tid + l * 256];
        }

        #pragma unroll
        for (int s = 0; s < 2; s++) {
            uint32_t afr[MFRAG][4];
            uint32_t bfr[NFRAG][2];
            #pragma unroll
            for (int mi = 0; mi < MFRAG; mi++) {
                int t8 = warp_m * MFRAG + mi;
                float4 fa = *(const float4*)&AsF[buf][(((s << 3) + t8) * 32 + lane) * 4];
                afr[mi][0] = __float_as_uint(fa.x);
                afr[mi][1] = __float_as_uint(fa.y);
                afr[mi][2] = __float_as_uint(fa.z);
                afr[mi][3] = __float_as_uint(fa.w);
            }
            #pragma unroll
            for (int ni2 = 0; ni2 < NFRAG / 2; ni2++) {
                int u2 = warp_n * (WN / 16) + ni2;
                float4 fb = *(const float4*)&BsF[buf][((s * (BN / 16) + u2) * 32 + lane) * 4];
                bfr[2 * ni2][0]     = __float_as_uint(fb.x);
                bfr[2 * ni2][1]     = __float_as_uint(fb.y);
                bfr[2 * ni2 + 1][0] = __float_as_uint(fb.z);
                bfr[2 * ni2 + 1][1] = __float_as_uint(fb.w);
            }
            #pragma unroll
            for (int mi = 0; mi < MFRAG; mi++)
                #pragma unroll
                for (int ni = 0; ni < NFRAG; ni++)
                    mma_tf32(acc[mi][ni], afr[mi], bfr[ni]);
        }

        if (t + 1 < ktiles) {
            int nb = buf ^ 1;
            ((float4*)AsF[nb])[tid]       = avp[0];
            ((float4*)AsF[nb])[tid + 256] = avp[1];
            #pragma unroll
            for (int l = 0; l < NB4; l++) ((float4*)BsF[nb])[tid + l * 256] = bvp[l];
            __syncthreads();
        }
    }

    int qm = lane >> 2;
    int qk = lane & 3;
    #pragma unroll
    for (int mi = 0; mi < MFRAG; mi++) {
        int r = br * 128 + warp_m * WM + mi * 16 + qm;
        #pragma unroll
        for (int ni = 0; ni < NFRAG; ni++) {
            int c = bc * BN + warp_n * WN + ni * 8 + 2 * qk;
            float2 v0 = make_float2(acc[mi][ni][0], acc[mi][ni][1]);
            float2 v1 = make_float2(acc[mi][ni][2], acc[mi][ni][3]);
            if (bias) {
                float2 bb = *(const float2*)&bias[c];
                v0.x += bb.x; v0.y += bb.y;
                v1.x += bb.x; v1.y += bb.y;
            }
            *(float2*)&C[(size_t)r * ldc + c] = v0;
            *(float2*)&C[(size_t)(r + 8) * ldc + c] = v1;
        }
    }
}

// ------------------------------ host orchestration ---------------------------
extern "C" void kernel_launch(void* const* d_in, const int* in_sizes, int n_in,
                              void* d_out, int out_size)
{
    const float* x       = (const float*)d_in[0];
    const int*   eidx    = (const int*)  d_in[1];
    const float* sage_Wl = (const float*)d_in[2];
    const float* sage_bl = (const float*)d_in[3];
    const float* sage_Wr = (const float*)d_in[4];
    const float* gcn1_W  = (const float*)d_in[5];
    const float* gcn1_b  = (const float*)d_in[6];
    const float* gcn2_W  = (const float*)d_in[7];
    const float* gcn2_b  = (const float*)d_in[8];
    const float* fc1_W   = (const float*)d_in[9];
    const float* fc1_b   = (const float*)d_in[10];
    const float* fc2_W   = (const float*)d_in[11];
    const float* fc2_b   = (const float*)d_in[12];
    const float* out_W   = (const float*)d_in[13];
    const float* out_b   = (const float*)d_in[14];
    float* out = (float*)d_out;

    const int* src = eidx;
    const int* dst = eidx + EE;

    float *P, *A, *B, *C, *D, *E, *Xt, *Wt, *Ht, *OWt;
    cudaGetSymbolAddress((void**)&P, g_P);
    cudaGetSymbolAddress((void**)&A, g_A);
    cudaGetSymbolAddress((void**)&B, g_B);
    cudaGetSymbolAddress((void**)&C, g_C);
    cudaGetSymbolAddress((void**)&D, g_D);
    cudaGetSymbolAddress((void**)&E, g_E);
    cudaGetSymbolAddress((void**)&Xt, g_Xt);
    cudaGetSymbolAddress((void**)&Wt, g_Wt);
    cudaGetSymbolAddress((void**)&Ht, g_Ht);
    cudaGetSymbolAddress((void**)&OWt, g_OWt);

    const int TPB = 256;

    // fused CSR build
    k_csr<<<1, 1024>>>(dst);
    k_fill<<<(EE + TPB - 1) / TPB, TPB>>>(src, dst);

    // pack operands of the big GEMMs
    k_packA<<<NN * NN / 4 / TPB, TPB>>>(x, Xt, NN, NN, NN);
    k_packB<<<NN * 512 / 4 / TPB, TPB>>>(sage_Wl, sage_Wr, 256, NN, 512, 256, 128, Wt);
    k_packB<<<128 * 16384 / 4 / TPB, TPB>>>(out_W, out_W, 16384, 128, 16384, 16384, 128, OWt);

    // P = x @ [Wl | Wr], split-K=2: grid (4,32,2), each z does 128 k-tiles
    {
        dim3 grid(512 / 128, NN / 128, 2);
        gemm_tf32p<128, 64, 32><<<grid, 256>>>(128, 256, (size_t)NN * 512,
                                               Xt, Wt, P, 512, nullptr);
    }

    // SAGE (gather, fused combine + split-K sum) -> B
    k_sage_gather<<<NN * 64 / TPB, TPB>>>(sage_bl);

    // GCN1: hw -> C, gather+bias+relu -> A
    {
        dim3 grid(256 / 64, NN / 64);
        sgemm64<<<grid, 256>>>(NN, 256, 256, B, 256, gcn1_W, 256, C, 256);
    }
    k_gcn_gather<<<NN * 64 / TPB, TPB>>>(C, gcn1_b, A, 6);

    // GCN2: hw -> D, gather+bias+relu -> E
    {
        dim3 grid(128 / 64, NN / 64);
        sgemm64<<<grid, 256>>>(NN, 128, 256, A, 256, gcn2_W, 128, D, 128);
    }
    k_gcn_gather<<<NN * 32 / TPB, TPB>>>(D, gcn2_b, E, 5);

    // fused fc1+fc2: E -> C
    k_fc12<<<NN / 64, 256>>>(E, fc1_W, fc1_b, fc2_W, fc2_b, C);

    // head GEMM (4096 x 16384 x 128)
    k_packA<<<NN * 128 / 4 / TPB, TPB>>>(C, Ht, NN, 128, 128);
    {
        dim3 grid(16384 / 128, NN / 128, 1);
        gemm_tf32p<128, 64, 32><<<grid, 256>>>(8, 8, 0, Ht, OWt, out, 16384, out_b);
    }
}

// round 11
// speedup vs baseline: 3.0702x; 1.0455x over previous
#include <cuda_runtime.h>
#include <cuda_bf16.h>
#include <math.h>
#include <stdint.h>

#define NN 4096
#define EE 65536

// ------------------- scratch (static device globals; no allocs) -------------
__device__ float g_P[NN * 1024];   // split-K=2: two 4096x512 partials
__device__ float g_A[NN * 256];
__device__ float g_B[NN * 256];
__device__ float g_C[NN * 256];
__device__ float g_D[NN * 128];
__device__ float g_E[NN * 128];
__device__ float g_dinv[NN];
__device__ int   g_rowptr[NN + 1];
__device__ int   g_fill[NN];
__device__ int   g_adj[EE];
// packed (tf32-rounded, fragment-tile-major) operands
__device__ float g_Xt[NN * NN];
__device__ float g_Wt[NN * 512];
__device__ float g_Ht[NN * 128];
__device__ float g_OWt[128 * 16384];

__device__ __forceinline__ float rtf32(float f) {
    uint32_t r;
    asm("cvt.rna.tf32.f32 %0, %1;" : "=r"(r) : "f"(f));
    return __uint_as_float(r);
}

// --------------------- fused CSR build (1 block, 1024 thr) ------------------
__global__ void k_csr(const int* __restrict__ dst) {
    __shared__ int sc[NN];
    __shared__ int ts[1024];
    int t = threadIdx.x;
    ((int4*)sc)[t] = make_int4(0, 0, 0, 0);
    __syncthreads();
    for (int e = t; e < EE; e += 1024) atomicAdd(&sc[dst[e]], 1);
    __syncthreads();
    int4 c = ((int4*)sc)[t];
    int s = c.x + c.y + c.z + c.w;
    ts[t] = s;
    __syncthreads();
    for (int off = 1; off < 1024; off <<= 1) {
        int x = (t >= off) ? ts[t - off] : 0;
        __syncthreads();
        ts[t] += x;
        __syncthreads();
    }
    int excl = ts[t] - s;
    int p0 = excl, p1 = excl + c.x, p2 = p1 + c.y, p3 = p2 + c.z;
    g_rowptr[4 * t + 0] = p0;  g_fill[4 * t + 0] = p0;
    g_rowptr[4 * t + 1] = p1;  g_fill[4 * t + 1] = p1;
    g_rowptr[4 * t + 2] = p2;  g_fill[4 * t + 2] = p2;
    g_rowptr[4 * t + 3] = p3;  g_fill[4 * t + 3] = p3;
    g_dinv[4 * t + 0] = rsqrtf((float)(c.x + 1));
    g_dinv[4 * t + 1] = rsqrtf((float)(c.y + 1));
    g_dinv[4 * t + 2] = rsqrtf((float)(c.z + 1));
    g_dinv[4 * t + 3] = rsqrtf((float)(c.w + 1));
    if (t == 1023) g_rowptr[NN] = ts[t];
}
__global__ void k_fill(const int* __restrict__ src, const int* __restrict__ dst) {
    int e = blockIdx.x * blockDim.x + threadIdx.x;
    if (e >= EE) return;
    int pos = atomicAdd(&g_fill[dst[e]], 1);
    g_adj[pos] = src[e];
}

// ---------------------- gather-based aggregations ----------------------------
__global__ void k_sage_gather(const float* __restrict__ bl) {
    int t = blockIdx.x * blockDim.x + threadIdx.x;
    if (t >= NN * 64) return;
    int v = t >> 6;
    int q = t & 63;
    int beg = g_rowptr[v], end = g_rowptr[v + 1];
    const float4* P4 = (const float4*)g_P;
    const float4* Q4 = P4 + NN * 128;
    float4 acc = make_float4(0.f, 0.f, 0.f, 0.f);
    for (int i = beg; i < end; i++) {
        int s = g_adj[i];
        float4 p = P4[(size_t)s * 128 + q];
        float4 p2 = Q4[(size_t)s * 128 + q];
        acc.x += p.x + p2.x; acc.y += p.y + p2.y;
        acc.z += p.z + p2.z; acc.w += p.w + p2.w;
    }
    float inv = 1.0f / fmaxf((float)(end - beg), 1.0f);
    float4 b = ((const float4*)bl)[q];
    float4 pr = P4[(size_t)v * 128 + 64 + q];
    float4 pr2 = Q4[(size_t)v * 128 + 64 + q];
    float4 r;
    r.x = fmaxf(acc.x * inv + b.x + pr.x + pr2.x, 0.f);
    r.y = fmaxf(acc.y * inv + b.y + pr.y + pr2.y, 0.f);
    r.z = fmaxf(acc.z * inv + b.z + pr.z + pr2.z, 0.f);
    r.w = fmaxf(acc.w * inv + b.w + pr.w + pr2.w, 0.f);
    ((float4*)g_B)[(size_t)v * 64 + q] = r;
}

__global__ void k_gcn_gather(const float* __restrict__ hw, const float* __restrict__ bias,
                             float* __restrict__ out, int hqsh) {
    int t = blockIdx.x * blockDim.x + threadIdx.x;
    if (t >= (NN << hqsh)) return;
    int v = t >> hqsh;
    int q = t & ((1 << hqsh) - 1);
    int Hq = 1 << hqsh;
    int beg = g_rowptr[v], end = g_rowptr[v + 1];
    float dv = g_dinv[v];
    const float4* H4 = (const float4*)hw;
    float4 self = H4[(size_t)v * Hq + q];
    float dv2 = dv * dv;
    float4 acc = make_float4(dv2 * self.x, dv2 * self.y, dv2 * self.z, dv2 * self.w);
    for (int i = beg; i < end; i++) {
        int s = g_adj[i];
        float nm = dv * g_dinv[s];
        float4 p = H4[(size_t)s * Hq + q];
        acc.x += nm * p.x; acc.y += nm * p.y; acc.z += nm * p.z; acc.w += nm * p.w;
    }
    float4 b = ((const float4*)bias)[q];
    float4 r;
    r.x = fmaxf(acc.x + b.x, 0.f);
    r.y = fmaxf(acc.y + b.y, 0.f);
    r.z = fmaxf(acc.z + b.z, 0.f);
    r.w = fmaxf(acc.w + b.w, 0.f);
    ((float4*)out)[(size_t)v * Hq + q] = r;
}

// ---- pack A operand: round to tf32 + permute to fragment-tile-major --------
__global__ void k_packA(const float* __restrict__ in, float* __restrict__ out,
                        int M, int K, int lda) {
    int o = blockIdx.x * blockDim.x + threadIdx.x;
    int total = (M * K) >> 2;
    if (o >= total) return;
    int perBlk = (K >> 4) << 9;
    int br = o / perBlk;
    int r = o - br * perBlk;
    int t = r >> 9;
    int q = r & 511;
    int s = q >> 8;
    int t8 = (q >> 5) & 7;
    int lane = q & 31;
    int m = br * 128 + t8 * 16 + (lane >> 2);
    int k = t * 16 + s * 8 + (lane & 3);
    const float* base = in + (size_t)m * lda + k;
    float4 v;
    v.x = rtf32(base[0]);
    v.y = rtf32(base[(size_t)8 * lda]);
    v.z = rtf32(base[4]);
    v.w = rtf32(base[(size_t)8 * lda + 4]);
    ((float4*)out)[o] = v;
}

// ---- pack B operand, PAIRED n-fragments ------------------------------------
__global__ void k_packB(const float* __restrict__ B0, const float* __restrict__ B1,
                        int nsplit, int K, int N, int ldb, int BN,
                        float* __restrict__ out) {
    int o = blockIdx.x * blockDim.x + threadIdx.x;
    int total = (K * N) >> 2;
    if (o >= total) return;
    int perBc = (K * BN) >> 2;
    int bc = o / perBc;
    int r = o - bc * perBc;
    int perTile = BN * 4;
    int t = r / perTile;
    int q = r - t * perTile;
    int s = q / (BN * 2);
    int q2 = q - s * (BN * 2);
    int u2 = q2 >> 5;
    int lane = q2 & 31;
    int k = t * 16 + s * 8 + (lane & 3);
    int n = bc * BN + u2 * 16 + (lane >> 2);
    const float* src = B0;
    if (n >= nsplit) { src = B1; n -= nsplit; }
    float4 v;
    v.x = rtf32(src[(size_t)k * ldb + n]);
    v.y = rtf32(src[(size_t)(k + 4) * ldb + n]);
    v.z = rtf32(src[(size_t)k * ldb + n + 8]);
    v.w = rtf32(src[(size_t)(k + 4) * ldb + n + 8]);
    ((float4*)out)[o] = v;
}

// ------------------- fp32 SIMT GEMM, 64x64x16 tiles (GCN layers) ------------
__global__ void __launch_bounds__(256, 4)
sgemm64(int M, int N, int K,
        const float* __restrict__ A, int lda,
        const float* __restrict__ B, int ldb,
        float* __restrict__ C, int ldc)
{
    const int BK = 16;
    __shared__ float As[2][BK][64];
    __shared__ float Bs[2][BK][64];

    int tid = threadIdx.x;
    int tx = tid & 15;
    int ty = tid >> 4;
    int row0 = blockIdx.y * 64;
    int col0 = blockIdx.x * 64;

    int am = tid >> 2;
    int ak = (tid & 3) << 2;
    int bk = tid >> 4;
    int bn = (tid & 15) << 2;

    const float* Aptr = A + (size_t)(row0 + am) * lda + ak;
    const float* Bptr = B + (size_t)bk * ldb + col0 + bn;
    size_t bstep = (size_t)BK * ldb;

    float4 av = *(const float4*)Aptr;
    float4 bv = *(const float4*)Bptr;
    As[0][ak + 0][am] = av.x;
    As[0][ak + 1][am] = av.y;
    As[0][ak + 2][am] = av.z;
    As[0][ak + 3][am] = av.w;
    *(float4*)&Bs[0][bk][bn] = bv;
    __syncthreads();

    float acc[4][4];
    #pragma unroll
    for (int i = 0; i < 4; i++)
        #pragma unroll
        for (int j = 0; j < 4; j++) acc[i][j] = 0.0f;

    int ntiles = K / BK;
    for (int t = 0; t < ntiles; t++) {
        int buf = t & 1;
        if (t + 1 < ntiles) {
            av = *(const float4*)(Aptr + (size_t)(t + 1) * BK);
            bv = *(const float4*)(Bptr + (size_t)(t + 1) * bstep);
        }
        #pragma unroll
        for (int k = 0; k < BK; k++) {
            float a[4], b[4];
            *(float4*)&a[0] = *(float4*)&As[buf][k][ty * 4];
            *(float4*)&b[0] = *(float4*)&Bs[buf][k][tx * 4];
            #pragma unroll
            for (int i = 0; i < 4; i++)
                #pragma unroll
                for (int j = 0; j < 4; j++)
                    acc[i][j] = fmaf(a[i], b[j], acc[i][j]);
        }
        if (t + 1 < ntiles) {
            int nb = buf ^ 1;
            As[nb][ak + 0][am] = av.x;
            As[nb][ak + 1][am] = av.y;
            As[nb][ak + 2][am] = av.z;
            As[nb][ak + 3][am] = av.w;
            *(float4*)&Bs[nb][bk][bn] = bv;
            __syncthreads();
        }
    }

    #pragma unroll
    for (int i = 0; i < 4; i++) {
        int gm = row0 + ty * 4 + i;
        int gn = col0 + tx * 4;
        *(float4*)&C[(size_t)gm * ldc + gn] =
            make_float4(acc[i][0], acc[i][1], acc[i][2], acc[i][3]);
    }
}

// ---------------- fused fc1+fc2: C = relu(relu(D@W1+b1)@W2+b2) --------------
__global__ void __launch_bounds__(256, 2)
k_fc12(const float* __restrict__ D,
       const float* __restrict__ W1, const float* __restrict__ b1,
       const float* __restrict__ W2, const float* __restrict__ b2,
       float* __restrict__ C)
{
    __shared__ float As[16][64];
    __shared__ float Bs[16][128];
    __shared__ float hs[64][132];

    int tid = threadIdx.x;
    int tx = tid & 15;
    int ty = tid >> 4;
    int row0 = blockIdx.x * 64;
    int am = tid >> 2;
    int ak = (tid & 3) << 2;

    float acc[4][8];
    #pragma unroll
    for (int i = 0; i < 4; i++)
        #pragma unroll
        for (int j = 0; j < 8; j++) acc[i][j] = 0.0f;

    for (int t = 0; t < 8; t++) {
        __syncthreads();
        {
            float4 av = *(const float4*)&D[(size_t)(row0 + am) * 128 + t * 16 + ak];
            As[ak + 0][am] = av.x;
            As[ak + 1][am] = av.y;
            As[ak + 2][am] = av.z;
            As[ak + 3][am] = av.w;
            #pragma unroll
            for (int l = 0; l < 2; l++) {
                int i = tid + l * 256;
                int bk = i >> 5;
                int bn = (i & 31) << 2;
                *(float4*)&Bs[bk][bn] = *(const float4*)&W1[(size_t)(t * 16 + bk) * 128 + bn];
            }
        }
        __syncthreads();
        #pragma unroll
        for (int k = 0; k < 16; k++) {
            float a[4], b[8];
            *(float4*)&a[0] = *(float4*)&As[k][ty * 4];
            *(float4*)&b[0] = *(float4*)&Bs[k][tx * 8];
            *(float4*)&b[4] = *(float4*)&Bs[k][tx * 8 + 4];
            #pragma unroll
            for (int i = 0; i < 4; i++)
                #pragma unroll
                for (int j = 0; j < 8; j++)
                    acc[i][j] = fmaf(a[i], b[j], acc[i][j]);
        }
    }
    __syncthreads();
    #pragma unroll
    for (int i = 0; i < 4; i++)
        #pragma unroll
        for (int j = 0; j < 8; j++)
            hs[ty * 4 + i][tx * 8 + j] = fmaxf(acc[i][j] + b1[tx * 8 + j], 0.0f);

    #pragma unroll
    for (int i = 0; i < 4; i++)
        #pragma unroll
        for (int j = 0; j < 8; j++) acc[i][j] = 0.0f;

    for (int t = 0; t < 8; t++) {
        __syncthreads();
        #pragma unroll
        for (int l = 0; l < 2; l++) {
            int i = tid + l * 256;
            int bk = i >> 5;
            int bn = (i & 31) << 2;
            *(float4*)&Bs[bk][bn] = *(const float4*)&W2[(size_t)(t * 16 + bk) * 128 + bn];
        }
        __syncthreads();
        #pragma unroll
        for (int k = 0; k < 16; k++) {
            int kk = t * 16 + k;
            float b[8];
            *(float4*)&b[0] = *(float4*)&Bs[k][tx * 8];
            *(float4*)&b[4] = *(float4*)&Bs[k][tx * 8 + 4];
            #pragma unroll
            for (int i = 0; i < 4; i++) {
                float a = hs[ty * 4 + i][kk];
                #pragma unroll
                for (int j = 0; j < 8; j++)
                    acc[i][j] = fmaf(a, b[j], acc[i][j]);
            }
        }
    }
    #pragma unroll
    for (int i = 0; i < 4; i++) {
        int gm = row0 + ty * 4 + i;
        #pragma unroll
        for (int j = 0; j < 8; j += 4) {
            int gn = tx * 8 + j;
            float4 v;
            v.x = fmaxf(acc[i][j + 0] + b2[gn + 0], 0.f);
            v.y = fmaxf(acc[i][j + 1] + b2[gn + 1], 0.f);
            v.z = fmaxf(acc[i][j + 2] + b2[gn + 2], 0.f);
            v.w = fmaxf(acc[i][j + 3] + b2[gn + 3], 0.f);
            *(float4*)&C[(size_t)gm * 128 + gn] = v;
        }
    }
}

// ------------- mma.sync tf32 GEMM, cp.async 4-stage pipeline ------------------
__device__ __forceinline__ void mma_tf32(float* c, const uint32_t* a, const uint32_t* b) {
    asm volatile(
        "mma.sync.aligned.m16n8k8.row.col.f32.tf32.tf32.f32 "
        "{%0,%1,%2,%3}, {%4,%5,%6,%7}, {%8,%9}, {%0,%1,%2,%3};"
        : "+f"(c[0]), "+f"(c[1]), "+f"(c[2]), "+f"(c[3])
        : "r"(a[0]), "r"(a[1]), "r"(a[2]), "r"(a[3]), "r"(b[0]), "r"(b[1]));
}
__device__ __forceinline__ void cp16(uint32_t s, const float4* g) {
    asm volatile("cp.async.cg.shared.global [%0], [%1], 16;" :: "r"(s), "l"(g));
}

template<int BN, int WM, int WN>
__global__ void __launch_bounds__(256, 2)
gemm_tf32p(int ktiles, int ktstride, size_t czstride,
           const float* __restrict__ At,
           const float* __restrict__ Bt,
           float* __restrict__ C, int ldc,
           const float* __restrict__ bias)
{
    const int MFRAG = WM / 16;
    const int NFRAG = WN / 8;
    const int WARPS_N = BN / WN;
    const int ATILE = 2048;           // floats per A k-tile
    const int BTILE = 16 * BN;        // floats per B k-tile
    const int NB = BTILE / 4 / 256;   // B float4 cp.async per thread

    extern __shared__ __align__(16) float smem[];
    float* AsF = smem;                  // 4 slots x ATILE
    float* BsF = smem + 4 * ATILE;      // 4 slots x BTILE

    int tid = threadIdx.x;
    int lane = tid & 31;
    int warp = tid >> 5;
    int warp_m = warp / WARPS_N;
    int warp_n = warp % WARPS_N;

    int br = blockIdx.y;
    int bc = blockIdx.x;
    int kt0 = blockIdx.z * ktiles;

    const float4* Ab = (const float4*)At + ((size_t)br * ktstride + kt0) * (ATILE / 4);
    const float4* Bb = (const float4*)Bt + ((size_t)bc * ktstride + kt0) * (BTILE / 4);
    C += (size_t)blockIdx.z * czstride;

    uint32_t sbase = (uint32_t)__cvta_generic_to_shared(smem);
    uint32_t sb_b = sbase + 4 * ATILE * 4;

    auto issue = [&](int t) {
        int slot = t & 3;
        const float4* An = Ab + (size_t)t * (ATILE / 4);
        const float4* Bn = Bb + (size_t)t * (BTILE / 4);
        uint32_t a0 = sbase + slot * (ATILE * 4) + tid * 16;
        cp16(a0, An + tid);
        cp16(a0 + 4096, An + tid + 256);
        uint32_t b0 = sb_b + slot * (BTILE * 4) + tid * 16;
        #pragma unroll
        for (int l = 0; l < NB; l++)
            cp16(b0 + l * 4096, Bn + tid + l * 256);
        asm volatile("cp.async.commit_group;" ::: "memory");
    };

    // prologue: 3 tiles in flight
    issue(0);
    if (ktiles > 1) issue(1);
    if (ktiles > 2) issue(2);

    float acc[MFRAG][NFRAG][4];
    #pragma unroll
    for (int mi = 0; mi < MFRAG; mi++)
        #pragma unroll
        for (int ni = 0; ni < NFRAG; ni++)
            #pragma unroll
            for (int j = 0; j < 4; j++) acc[mi][ni][j] = 0.0f;

    for (int t = 0; t < ktiles; t++) {
        int rem = ktiles - 1 - t;
        if (rem >= 2)      asm volatile("cp.async.wait_group 2;" ::: "memory");
        else if (rem == 1) asm volatile("cp.async.wait_group 1;" ::: "memory");
        else               asm volatile("cp.async.wait_group 0;" ::: "memory");
        __syncthreads();

        if (t + 3 < ktiles) issue(t + 3);   // slot (t+3)&3 == (t-1)&3: drained by barrier above

        int slot = t & 3;
        const float* As = AsF + slot * ATILE;
        const float* Bs = BsF + slot * BTILE;

        #pragma unroll
        for (int s = 0; s < 2; s++) {
            uint32_t afr[MFRAG][4];
            uint32_t bfr[NFRAG][2];
            #pragma unroll
            for (int mi = 0; mi < MFRAG; mi++) {
                int t8 = warp_m * MFRAG + mi;
                float4 fa = *(const float4*)&As[(((s << 3) + t8) * 32 + lane) * 4];
                afr[mi][0] = __float_as_uint(fa.x);
                afr[mi][1] = __float_as_uint(fa.y);
                afr[mi][2] = __float_as_uint(fa.z);
                afr[mi][3] = __float_as_uint(fa.w);
            }
            #pragma unroll
            for (int ni2 = 0; ni2 < NFRAG / 2; ni2++) {
                int u2 = warp_n * (WN / 16) + ni2;
                float4 fb = *(const float4*)&Bs[((s * (BN / 16) + u2) * 32 + lane) * 4];
                bfr[2 * ni2][0]     = __float_as_uint(fb.x);
                bfr[2 * ni2][1]     = __float_as_uint(fb.y);
                bfr[2 * ni2 + 1][0] = __float_as_uint(fb.z);
                bfr[2 * ni2 + 1][1] = __float_as_uint(fb.w);
            }
            #pragma unroll
            for (int mi = 0; mi < MFRAG; mi++)
                #pragma unroll
                for (int ni = 0; ni < NFRAG; ni++)
                    mma_tf32(acc[mi][ni], afr[mi], bfr[ni]);
        }
    }

    int qm = lane >> 2;
    int qk = lane & 3;
    #pragma unroll
    for (int mi = 0; mi < MFRAG; mi++) {
        int r = br * 128 + warp_m * WM + mi * 16 + qm;
        #pragma unroll
        for (int ni = 0; ni < NFRAG; ni++) {
            int c = bc * BN + warp_n * WN + ni * 8 + 2 * qk;
            float2 v0 = make_float2(acc[mi][ni][0], acc[mi][ni][1]);
            float2 v1 = make_float2(acc[mi][ni][2], acc[mi][ni][3]);
            if (bias) {
                float2 bb = *(const float2*)&bias[c];
                v0.x += bb.x; v0.y += bb.y;
                v1.x += bb.x; v1.y += bb.y;
            }
            *(float2*)&C[(size_t)r * ldc + c] = v0;
            *(float2*)&C[(size_t)(r + 8) * ldc + c] = v1;
        }
    }
}

// ------------------------------ host orchestration ---------------------------
extern "C" void kernel_launch(void* const* d_in, const int* in_sizes, int n_in,
                              void* d_out, int out_size)
{
    const float* x       = (const float*)d_in[0];
    const int*   eidx    = (const int*)  d_in[1];
    const float* sage_Wl = (const float*)d_in[2];
    const float* sage_bl = (const float*)d_in[3];
    const float* sage_Wr = (const float*)d_in[4];
    const float* gcn1_W  = (const float*)d_in[5];
    const float* gcn1_b  = (const float*)d_in[6];
    const float* gcn2_W  = (const float*)d_in[7];
    const float* gcn2_b  = (const float*)d_in[8];
    const float* fc1_W   = (const float*)d_in[9];
    const float* fc1_b   = (const float*)d_in[10];
    const float* fc2_W   = (const float*)d_in[11];
    const float* fc2_b   = (const float*)d_in[12];
    const float* out_W   = (const float*)d_in[13];
    const float* out_b   = (const float*)d_in[14];
    float* out = (float*)d_out;

    const int* src = eidx;
    const int* dst = eidx + EE;

    float *P, *A, *B, *C, *D, *E, *Xt, *Wt, *Ht, *OWt;
    cudaGetSymbolAddress((void**)&P, g_P);
    cudaGetSymbolAddress((void**)&A, g_A);
    cudaGetSymbolAddress((void**)&B, g_B);
    cudaGetSymbolAddress((void**)&C, g_C);
    cudaGetSymbolAddress((void**)&D, g_D);
    cudaGetSymbolAddress((void**)&E, g_E);
    cudaGetSymbolAddress((void**)&Xt, g_Xt);
    cudaGetSymbolAddress((void**)&Wt, g_Wt);
    cudaGetSymbolAddress((void**)&Ht, g_Ht);
    cudaGetSymbolAddress((void**)&OWt, g_OWt);

    const int TPB = 256;
    const int GSMEM = 4 * (2048 + 2048) * 4;   // 64KB: 4-slot A+B ring (BN=128)
    static int smem_set = 0;
    cudaFuncSetAttribute(gemm_tf32p<128, 64, 32>,
                         cudaFuncAttributeMaxDynamicSharedMemorySize, GSMEM);
    (void)smem_set;

    // fused CSR build
    k_csr<<<1, 1024>>>(dst);
    k_fill<<<(EE + TPB - 1) / TPB, TPB>>>(src, dst);

    // pack operands of the big GEMMs
    k_packA<<<NN * NN / 4 / TPB, TPB>>>(x, Xt, NN, NN, NN);
    k_packB<<<NN * 512 / 4 / TPB, TPB>>>(sage_Wl, sage_Wr, 256, NN, 512, 256, 128, Wt);
    k_packB<<<128 * 16384 / 4 / TPB, TPB>>>(out_W, out_W, 16384, 128, 16384, 16384, 128, OWt);

    // P = x @ [Wl | Wr], split-K=2: grid (4,32,2)
    {
        dim3 grid(512 / 128, NN / 128, 2);
        gemm_tf32p<128, 64, 32><<<grid, 256, GSMEM>>>(128, 256, (size_t)NN * 512,
                                                      Xt, Wt, P, 512, nullptr);
    }

    // SAGE (gather, fused combine + split-K sum) -> B
    k_sage_gather<<<NN * 64 / TPB, TPB>>>(sage_bl);

    // GCN1: hw -> C, gather+bias+relu -> A
    {
        dim3 grid(256 / 64, NN / 64);
        sgemm64<<<grid, 256>>>(NN, 256, 256, B, 256, gcn1_W, 256, C, 256);
    }
    k_gcn_gather<<<NN * 64 / TPB, TPB>>>(C, gcn1_b, A, 6);

    // GCN2: hw -> D, gather+bias+relu -> E
    {
        dim3 grid(128 / 64, NN / 64);
        sgemm64<<<grid, 256>>>(NN, 128, 256, A, 256, gcn2_W, 128, D, 128);
    }
    k_gcn_gather<<<NN * 32 / TPB, TPB>>>(D, gcn2_b, E, 5);

    // fused fc1+fc2: E -> C
    k_fc12<<<NN / 64, 256>>>(E, fc1_W, fc1_b, fc2_W, fc2_b, C);

    // head GEMM (4096 x 16384 x 128)
    k_packA<<<NN * 128 / 4 / TPB, TPB>>>(C, Ht, NN, 128, 128);
    {
        dim3 grid(16384 / 128, NN / 128, 1);
        gemm_tf32p<128, 64, 32><<<grid, 256, GSMEM>>>(8, 8, 0, Ht, OWt, out, 16384, out_b);
    }
}

// round 13
// speedup vs baseline: 3.9382x; 1.2827x over previous
#include <cuda_runtime.h>
#include <cuda_fp16.h>
#include <math.h>
#include <stdint.h>

#define NN 4096
#define EE 65536

// ------------------- scratch (static device globals; no allocs) -------------
__device__ float g_P[NN * 1024];   // split-K=2 partials (reduced in k_padd)
__device__ float g_A[NN * 256];
__device__ float g_B[NN * 256];
__device__ float g_C[NN * 256];
__device__ float g_D[NN * 128];
__device__ float g_E[NN * 128];
__device__ float g_dinv[NN];
__device__ int   g_rowptr[NN + 1];
__device__ int   g_fill[NN];
__device__ int   g_adj[EE];
// packed fp16 fragment-major operands (stored as uint32 = half2)
__device__ uint32_t g_Xt[NN * NN / 2];
__device__ uint32_t g_Wt[NN * 512 / 2];
__device__ uint32_t g_Ht[NN * 128 / 2];
__device__ uint32_t g_OWt[128 * 16384 / 2];

__device__ __forceinline__ uint32_t pack2h(float a, float b) {
    uint32_t lo = __half_as_ushort(__float2half_rn(a));
    uint32_t hi = __half_as_ushort(__float2half_rn(b));
    return lo | (hi << 16);
}

// --------------------- fused CSR build (1 block, 1024 thr) ------------------
__global__ void k_csr(const int* __restrict__ dst) {
    __shared__ int sc[NN];
    __shared__ int ts[1024];
    int t = threadIdx.x;
    ((int4*)sc)[t] = make_int4(0, 0, 0, 0);
    __syncthreads();
    for (int e = t; e < EE; e += 1024) atomicAdd(&sc[dst[e]], 1);
    __syncthreads();
    int4 c = ((int4*)sc)[t];
    int s = c.x + c.y + c.z + c.w;
    ts[t] = s;
    __syncthreads();
    for (int off = 1; off < 1024; off <<= 1) {
        int x = (t >= off) ? ts[t - off] : 0;
        __syncthreads();
        ts[t] += x;
        __syncthreads();
    }
    int excl = ts[t] - s;
    int p0 = excl, p1 = excl + c.x, p2 = p1 + c.y, p3 = p2 + c.z;
    g_rowptr[4 * t + 0] = p0;  g_fill[4 * t + 0] = p0;
    g_rowptr[4 * t + 1] = p1;  g_fill[4 * t + 1] = p1;
    g_rowptr[4 * t + 2] = p2;  g_fill[4 * t + 2] = p2;
    g_rowptr[4 * t + 3] = p3;  g_fill[4 * t + 3] = p3;
    g_dinv[4 * t + 0] = rsqrtf((float)(c.x + 1));
    g_dinv[4 * t + 1] = rsqrtf((float)(c.y + 1));
    g_dinv[4 * t + 2] = rsqrtf((float)(c.z + 1));
    g_dinv[4 * t + 3] = rsqrtf((float)(c.w + 1));
    if (t == 1023) g_rowptr[NN] = ts[t];
}
__global__ void k_fill(const int* __restrict__ src, const int* __restrict__ dst) {
    int e = blockIdx.x * blockDim.x + threadIdx.x;
    if (e >= EE) return;
    int pos = atomicAdd(&g_fill[dst[e]], 1);
    g_adj[pos] = src[e];
}

// ---- reduce split-K partials: P0 += P1 --------------------------------------
__global__ void k_padd() {
    int i = blockIdx.x * blockDim.x + threadIdx.x;
    if (i >= NN * 128) return;
    float4 a = ((float4*)g_P)[i];
    float4 b = ((const float4*)g_P)[NN * 128 + i];
    a.x += b.x; a.y += b.y; a.z += b.z; a.w += b.w;
    ((float4*)g_P)[i] = a;
}

// ---------------------- gather-based aggregations ----------------------------
__global__ void k_sage_gather(const float* __restrict__ bl) {
    int t = blockIdx.x * blockDim.x + threadIdx.x;
    if (t >= NN * 64) return;
    int v = t >> 6;
    int q = t & 63;
    int beg = g_rowptr[v], end = g_rowptr[v + 1];
    const float4* P4 = (const float4*)g_P;
    float4 acc = make_float4(0.f, 0.f, 0.f, 0.f);
    for (int i = beg; i < end; i++) {
        int s = g_adj[i];
        float4 p = P4[(size_t)s * 128 + q];
        acc.x += p.x; acc.y += p.y; acc.z += p.z; acc.w += p.w;
    }
    float inv = 1.0f / fmaxf((float)(end - beg), 1.0f);
    float4 b = ((const float4*)bl)[q];
    float4 pr = P4[(size_t)v * 128 + 64 + q];
    float4 r;
    r.x = fmaxf(acc.x * inv + b.x + pr.x, 0.f);
    r.y = fmaxf(acc.y * inv + b.y + pr.y, 0.f);
    r.z = fmaxf(acc.z * inv + b.z + pr.z, 0.f);
    r.w = fmaxf(acc.w * inv + b.w + pr.w, 0.f);
    ((float4*)g_B)[(size_t)v * 64 + q] = r;
}

__global__ void k_gcn_gather(const float* __restrict__ hw, const float* __restrict__ bias,
                             float* __restrict__ out, int hqsh) {
    int t = blockIdx.x * blockDim.x + threadIdx.x;
    if (t >= (NN << hqsh)) return;
    int v = t >> hqsh;
    int q = t & ((1 << hqsh) - 1);
    int Hq = 1 << hqsh;
    int beg = g_rowptr[v], end = g_rowptr[v + 1];
    float dv = g_dinv[v];
    const float4* H4 = (const float4*)hw;
    float4 self = H4[(size_t)v * Hq + q];
    float dv2 = dv * dv;
    float4 acc = make_float4(dv2 * self.x, dv2 * self.y, dv2 * self.z, dv2 * self.w);
    for (int i = beg; i < end; i++) {
        int s = g_adj[i];
        float nm = dv * g_dinv[s];
        float4 p = H4[(size_t)s * Hq + q];
        acc.x += nm * p.x; acc.y += nm * p.y; acc.z += nm * p.z; acc.w += nm * p.w;
    }
    float4 b = ((const float4*)bias)[q];
    float4 r;
    r.x = fmaxf(acc.x + b.x, 0.f);
    r.y = fmaxf(acc.y + b.y, 0.f);
    r.z = fmaxf(acc.z + b.z, 0.f);
    r.w = fmaxf(acc.w + b.w, 0.f);
    ((float4*)out)[(size_t)v * Hq + q] = r;
}

// ---- pack A to fp16 fragment-major (m16n8k16) -------------------------------
// Per (row-block br, 32-k tile kt): 2048 uint32 laid out as
// ((s*8 + t8)*32 + lane)*4 + reg, lane = qm*4+qk:
//   reg0: (m = t8*16+qm, k = 16s+2qk) pair; reg1: m+8; reg2: k+8; reg3: m+8,k+8.
__global__ void k_packAh(const float* __restrict__ in, uint32_t* __restrict__ out,
                         int K, int lda) {
    int o = blockIdx.x * blockDim.x + threadIdx.x;
    int ktp = K >> 5;
    int perBlk = ktp << 11;
    int br = o / perBlk;
    int r = o - br * perBlk;
    int kt = r >> 11;
    int q = r & 2047;
    int reg = q & 3;
    int lane = (q >> 2) & 31;
    int t8 = (q >> 7) & 7;
    int s = q >> 10;
    int qm = lane >> 2;
    int qk = lane & 3;
    int m = br * 128 + t8 * 16 + qm + (reg & 1) * 8;
    int k = kt * 32 + s * 16 + 2 * qk + (reg & 2) * 4;
    float2 v = *(const float2*)&in[(size_t)m * lda + k];
    out[o] = pack2h(v.x, v.y);
}

// ---- pack B to fp16 fragment-major, PAIRED n-fragments (BN=128) ------------
// Per (col-block bc, 32-k tile): 2048 uint32 as ((s*8 + u2)*32 + lane)*4 + reg:
//   reg0: frag 2u2 b0 (k=16s+2qk, n=16u2+qm); reg1: frag 2u2 b1 (k+8);
//   reg2: frag 2u2+1 b0 (n+8);                reg3: frag 2u2+1 b1.
__global__ void k_packBh(const float* __restrict__ B0, const float* __restrict__ B1,
                         int nsplit, int K, int ldb, uint32_t* __restrict__ out) {
    int o = blockIdx.x * blockDim.x + threadIdx.x;
    int ktp = K >> 5;
    int perBc = ktp << 11;
    int bc = o / perBc;
    int r = o - bc * perBc;
    int kt = r >> 11;
    int q = r & 2047;
    int reg = q & 3;
    int lane = (q >> 2) & 31;
    int u2 = (q >> 7) & 7;
    int s = q >> 10;
    int qm = lane >> 2;
    int qk = lane & 3;
    int n = bc * 128 + u2 * 16 + qm + ((reg >> 1) & 1) * 8;
    int k = kt * 32 + s * 16 + 2 * qk + (reg & 1) * 8;
    const float* src = B0;
    if (n >= nsplit) { src = B1; n -= nsplit; }
    float v0 = src[(size_t)k * ldb + n];
    float v1 = src[(size_t)(k + 1) * ldb + n];
    out[o] = pack2h(v0, v1);
}

// ------------------- fp32 SIMT GEMM, 64x64x16 tiles (GCN layers) ------------
__global__ void __launch_bounds__(256, 4)
sgemm64(int M, int N, int K,
        const float* __restrict__ A, int lda,
        const float* __restrict__ B, int ldb,
        float* __restrict__ C, int ldc)
{
    const int BK = 16;
    __shared__ float As[2][BK][64];
    __shared__ float Bs[2][BK][64];

    int tid = threadIdx.x;
    int tx = tid & 15;
    int ty = tid >> 4;
    int row0 = blockIdx.y * 64;
    int col0 = blockIdx.x * 64;

    int am = tid >> 2;
    int ak = (tid & 3) << 2;
    int bk = tid >> 4;
    int bn = (tid & 15) << 2;

    const float* Aptr = A + (size_t)(row0 + am) * lda + ak;
    const float* Bptr = B + (size_t)bk * ldb + col0 + bn;
    size_t bstep = (size_t)BK * ldb;

    float4 av = *(const float4*)Aptr;
    float4 bv = *(const float4*)Bptr;
    As[0][ak + 0][am] = av.x;
    As[0][ak + 1][am] = av.y;
    As[0][ak + 2][am] = av.z;
    As[0][ak + 3][am] = av.w;
    *(float4*)&Bs[0][bk][bn] = bv;
    __syncthreads();

    float acc[4][4];
    #pragma unroll
    for (int i = 0; i < 4; i++)
        #pragma unroll
        for (int j = 0; j < 4; j++) acc[i][j] = 0.0f;

    int ntiles = K / BK;
    for (int t = 0; t < ntiles; t++) {
        int buf = t & 1;
        if (t + 1 < ntiles) {
            av = *(const float4*)(Aptr + (size_t)(t + 1) * BK);
            bv = *(const float4*)(Bptr + (size_t)(t + 1) * bstep);
        }
        #pragma unroll
        for (int k = 0; k < BK; k++) {
            float a[4], b[4];
            *(float4*)&a[0] = *(float4*)&As[buf][k][ty * 4];
            *(float4*)&b[0] = *(float4*)&Bs[buf][k][tx * 4];
            #pragma unroll
            for (int i = 0; i < 4; i++)
                #pragma unroll
                for (int j = 0; j < 4; j++)
                    acc[i][j] = fmaf(a[i], b[j], acc[i][j]);
        }
        if (t + 1 < ntiles) {
            int nb = buf ^ 1;
            As[nb][ak + 0][am] = av.x;
            As[nb][ak + 1][am] = av.y;
            As[nb][ak + 2][am] = av.z;
            As[nb][ak + 3][am] = av.w;
            *(float4*)&Bs[nb][bk][bn] = bv;
            __syncthreads();
        }
    }

    #pragma unroll
    for (int i = 0; i < 4; i++) {
        int gm = row0 + ty * 4 + i;
        int gn = col0 + tx * 4;
        *(float4*)&C[(size_t)gm * ldc + gn] =
            make_float4(acc[i][0], acc[i][1], acc[i][2], acc[i][3]);
    }
}

// ---------------- fused fc1+fc2: C = relu(relu(D@W1+b1)@W2+b2) --------------
__global__ void __launch_bounds__(256, 2)
k_fc12(const float* __restrict__ D,
       const float* __restrict__ W1, const float* __restrict__ b1,
       const float* __restrict__ W2, const float* __restrict__ b2,
       float* __restrict__ C)
{
    __shared__ float As[16][64];
    __shared__ float Bs[16][128];
    __shared__ float hs[64][132];

    int tid = threadIdx.x;
    int tx = tid & 15;
    int ty = tid >> 4;
    int row0 = blockIdx.x * 64;
    int am = tid >> 2;
    int ak = (tid & 3) << 2;

    float acc[4][8];
    #pragma unroll
    for (int i = 0; i < 4; i++)
        #pragma unroll
        for (int j = 0; j < 8; j++) acc[i][j] = 0.0f;

    for (int t = 0; t < 8; t++) {
        __syncthreads();
        {
            float4 av = *(const float4*)&D[(size_t)(row0 + am) * 128 + t * 16 + ak];
            As[ak + 0][am] = av.x;
            As[ak + 1][am] = av.y;
            As[ak + 2][am] = av.z;
            As[ak + 3][am] = av.w;
            #pragma unroll
            for (int l = 0; l < 2; l++) {
                int i = tid + l * 256;
                int bk = i >> 5;
                int bn = (i & 31) << 2;
                *(float4*)&Bs[bk][bn] = *(const float4*)&W1[(size_t)(t * 16 + bk) * 128 + bn];
            }
        }
        __syncthreads();
        #pragma unroll
        for (int k = 0; k < 16; k++) {
            float a[4], b[8];
            *(float4*)&a[0] = *(float4*)&As[k][ty * 4];
            *(float4*)&b[0] = *(float4*)&Bs[k][tx * 8];
            *(float4*)&b[4] = *(float4*)&Bs[k][tx * 8 + 4];
            #pragma unroll
            for (int i = 0; i < 4; i++)
                #pragma unroll
                for (int j = 0; j < 8; j++)
                    acc[i][j] = fmaf(a[i], b[j], acc[i][j]);
        }
    }
    __syncthreads();
    #pragma unroll
    for (int i = 0; i < 4; i++)
        #pragma unroll
        for (int j = 0; j < 8; j++)
            hs[ty * 4 + i][tx * 8 + j] = fmaxf(acc[i][j] + b1[tx * 8 + j], 0.0f);

    #pragma unroll
    for (int i = 0; i < 4; i++)
        #pragma unroll
        for (int j = 0; j < 8; j++) acc[i][j] = 0.0f;

    for (int t = 0; t < 8; t++) {
        __syncthreads();
        #pragma unroll
        for (int l = 0; l < 2; l++) {
            int i = tid + l * 256;
            int bk = i >> 5;
            int bn = (i & 31) << 2;
            *(float4*)&Bs[bk][bn] = *(const float4*)&W2[(size_t)(t * 16 + bk) * 128 + bn];
        }
        __syncthreads();
        #pragma unroll
        for (int k = 0; k < 16; k++) {
            int kk = t * 16 + k;
            float b[8];
            *(float4*)&b[0] = *(float4*)&Bs[k][tx * 8];
            *(float4*)&b[4] = *(float4*)&Bs[k][tx * 8 + 4];
            #pragma unroll
            for (int i = 0; i < 4; i++) {
                float a = hs[ty * 4 + i][kk];
                #pragma unroll
                for (int j = 0; j < 8; j++)
                    acc[i][j] = fmaf(a, b[j], acc[i][j]);
            }
        }
    }
    #pragma unroll
    for (int i = 0; i < 4; i++) {
        int gm = row0 + ty * 4 + i;
        #pragma unroll
        for (int j = 0; j < 8; j += 4) {
            int gn = tx * 8 + j;
            float4 v;
            v.x = fmaxf(acc[i][j + 0] + b2[gn + 0], 0.f);
            v.y = fmaxf(acc[i][j + 1] + b2[gn + 1], 0.f);
            v.z = fmaxf(acc[i][j + 2] + b2[gn + 2], 0.f);
            v.w = fmaxf(acc[i][j + 3] + b2[gn + 3], 0.f);
            *(float4*)&C[(size_t)gm * 128 + gn] = v;
        }
    }
}

// ------------- fp16 mma.sync GEMM (m16n8k16), cp.async 4-stage ---------------
__device__ __forceinline__ void mma_f16(float* c, const uint32_t* a, const uint32_t* b) {
    asm volatile(
        "mma.sync.aligned.m16n8k16.row.col.f32.f16.f16.f32 "
        "{%0,%1,%2,%3}, {%4,%5,%6,%7}, {%8,%9}, {%0,%1,%2,%3};"
        : "+f"(c[0]), "+f"(c[1]), "+f"(c[2]), "+f"(c[3])
        : "r"(a[0]), "r"(a[1]), "r"(a[2]), "r"(a[3]), "r"(b[0]), "r"(b[1]));
}
__device__ __forceinline__ void cp16(uint32_t s, const void* g) {
    asm volatile("cp.async.cg.shared.global [%0], [%1], 16;" :: "r"(s), "l"(g));
}

// BN=128, WM=64, WN=32 (8 warps = 2x4). K-tile = 32 halves.
// A tile = 2048 u32, B tile = 2048 u32; 4-slot ring = 64KB dynamic smem.
__global__ void __launch_bounds__(256, 2)
gemm_fp16p(int ktiles, int ktstride, size_t czstride,
           const uint32_t* __restrict__ At,
           const uint32_t* __restrict__ Bt,
           float* __restrict__ C, int ldc,
           const float* __restrict__ bias)
{
    const int MFRAG = 4;   // WM/16
    const int NFRAG = 4;   // WN/8
    const int TILE = 2048; // u32 per k-tile (A and B each)

    extern __shared__ __align__(16) uint32_t smem[];
    uint32_t* AsF = smem;
    uint32_t* BsF = smem + 4 * TILE;

    int tid = threadIdx.x;
    int lane = tid & 31;
    int warp = tid >> 5;
    int warp_m = warp >> 2;   // 0..1
    int warp_n = warp & 3;    // 0..3

    int br = blockIdx.y;
    int bc = blockIdx.x;
    int kt0 = blockIdx.z * ktiles;

    const uint4* Ab = (const uint4*)At + ((size_t)br * ktstride + kt0) * (TILE / 4);
    const uint4* Bb = (const uint4*)Bt + ((size_t)bc * ktstride + kt0) * (TILE / 4);
    C += (size_t)blockIdx.z * czstride;

    uint32_t sbase = (uint32_t)__cvta_generic_to_shared(smem);
    uint32_t sb_b = sbase + 4 * TILE * 4;

    auto issue = [&](int t) {
        int slot = t & 3;
        const uint4* An = Ab + (size_t)t * (TILE / 4);
        const uint4* Bn = Bb + (size_t)t * (TILE / 4);
        uint32_t a0 = sbase + slot * (TILE * 4) + tid * 16;
        cp16(a0, An + tid);
        cp16(a0 + 4096, An + tid + 256);
        uint32_t b0 = sb_b + slot * (TILE * 4) + tid * 16;
        cp16(b0, Bn + tid);
        cp16(b0 + 4096, Bn + tid + 256);
        asm volatile("cp.async.commit_group;" ::: "memory");
    };

    issue(0);
    if (ktiles > 1) issue(1);
    if (ktiles > 2) issue(2);

    float acc[MFRAG][NFRAG][4];
    #pragma unroll
    for (int mi = 0; mi < MFRAG; mi++)
        #pragma unroll
        for (int ni = 0; ni < NFRAG; ni++)
            #pragma unroll
            for (int j = 0; j < 4; j++) acc[mi][ni][j] = 0.0f;

    for (int t = 0; t < ktiles; t++) {
        int rem = ktiles - 1 - t;
        if (rem >= 2)      asm volatile("cp.async.wait_group 2;" ::: "memory");
        else if (rem == 1) asm volatile("cp.async.wait_group 1;" ::: "memory");
        else               asm volatile("cp.async.wait_group 0;" ::: "memory");
        __syncthreads();

        if (t + 3 < ktiles) issue(t + 3);

        int slot = t & 3;
        const uint32_t* As = AsF + slot * TILE;
        const uint32_t* Bs = BsF + slot * TILE;

        #pragma unroll
        for (int s = 0; s < 2; s++) {
            uint32_t afr[MFRAG][4];
            uint32_t bfr[NFRAG][2];
            #pragma unroll
            for (int mi = 0; mi < MFRAG; mi++) {
                int t8 = warp_m * MFRAG + mi;
                uint4 fa = *(const uint4*)&As[(((s << 3) + t8) * 32 + lane) * 4];
                afr[mi][0] = fa.x; afr[mi][1] = fa.y;
                afr[mi][2] = fa.z; afr[mi][3] = fa.w;
            }
            #pragma unroll
            for (int ni2 = 0; ni2 < NFRAG / 2; ni2++) {
                int u2 = warp_n * (NFRAG / 2) + ni2;
                uint4 fb = *(const uint4*)&Bs[(((s << 3) + u2) * 32 + lane) * 4];
                bfr[2 * ni2][0]     = fb.x;
                bfr[2 * ni2][1]     = fb.y;
                bfr[2 * ni2 + 1][0] = fb.z;
                bfr[2 * ni2 + 1][1] = fb.w;
            }
            #pragma unroll
            for (int mi = 0; mi < MFRAG; mi++)
                #pragma unroll
                for (int ni = 0; ni < NFRAG; ni++)
                    mma_f16(acc[mi][ni], afr[mi], bfr[ni]);
        }
    }

    int qm = lane >> 2;
    int qk = lane & 3;
    #pragma unroll
    for (int mi = 0; mi < MFRAG; mi++) {
        int r = br * 128 + warp_m * 64 + mi * 16 + qm;
        #pragma unroll
        for (int ni = 0; ni < NFRAG; ni++) {
            int c = bc * 128 + warp_n * 32 + ni * 8 + 2 * qk;
            float2 v0 = make_float2(acc[mi][ni][0], acc[mi][ni][1]);
            float2 v1 = make_float2(acc[mi][ni][2], acc[mi][ni][3]);
            if (bias) {
                float2 bb = *(const float2*)&bias[c];
                v0.x += bb.x; v0.y += bb.y;
                v1.x += bb.x; v1.y += bb.y;
            }
            *(float2*)&C[(size_t)r * ldc + c] = v0;
            *(float2*)&C[(size_t)(r + 8) * ldc + c] = v1;
        }
    }
}

// ------------------------------ host orchestration ---------------------------
extern "C" void kernel_launch(void* const* d_in, const int* in_sizes, int n_in,
                              void* d_out, int out_size)
{
    const float* x       = (const float*)d_in[0];
    const int*   eidx    = (const int*)  d_in[1];
    const float* sage_Wl = (const float*)d_in[2];
    const float* sage_bl = (const float*)d_in[3];
    const float* sage_Wr = (const float*)d_in[4];
    const float* gcn1_W  = (const float*)d_in[5];
    const float* gcn1_b  = (const float*)d_in[6];
    const float* gcn2_W  = (const float*)d_in[7];
    const float* gcn2_b  = (const float*)d_in[8];
    const float* fc1_W   = (const float*)d_in[9];
    const float* fc1_b   = (const float*)d_in[10];
    const float* fc2_W   = (const float*)d_in[11];
    const float* fc2_b   = (const float*)d_in[12];
    const float* out_W   = (const float*)d_in[13];
    const float* out_b   = (const float*)d_in[14];
    float* out = (float*)d_out;

    const int* src = eidx;
    const int* dst = eidx + EE;

    float *P, *A, *B, *C, *D, *E;
    uint32_t *Xt, *Wt, *Ht, *OWt;
    cudaGetSymbolAddress((void**)&P, g_P);
    cudaGetSymbolAddress((void**)&A, g_A);
    cudaGetSymbolAddress((void**)&B, g_B);
    cudaGetSymbolAddress((void**)&C, g_C);
    cudaGetSymbolAddress((void**)&D, g_D);
    cudaGetSymbolAddress((void**)&E, g_E);
    cudaGetSymbolAddress((void**)&Xt, g_Xt);
    cudaGetSymbolAddress((void**)&Wt, g_Wt);
    cudaGetSymbolAddress((void**)&Ht, g_Ht);
    cudaGetSymbolAddress((void**)&OWt, g_OWt);

    const int TPB = 256;
    const int GSMEM = 8 * 2048 * 4;   // 64KB: 4-slot A+B ring
    cudaFuncSetAttribute(gemm_fp16p, cudaFuncAttributeMaxDynamicSharedMemorySize, GSMEM);

    // fused CSR build
    k_csr<<<1, 1024>>>(dst);
    k_fill<<<(EE + TPB - 1) / TPB, TPB>>>(src, dst);

    // pack operands (fp16 fragment-major)
    k_packAh<<<NN * NN / 2 / TPB, TPB>>>(x, Xt, NN, NN);
    k_packBh<<<NN * 512 / 2 / TPB, TPB>>>(sage_Wl, sage_Wr, 256, NN, 256, Wt);
    k_packBh<<<128 * 16384 / 2 / TPB, TPB>>>(out_W, out_W, 16384, 128, 16384, OWt);

    // P = x @ [Wl | Wr], split-K=2: grid (4,32,2), 64 k-tiles of 32 each
    {
        dim3 grid(512 / 128, NN / 128, 2);
        gemm_fp16p<<<grid, 256, GSMEM>>>(64, 128, (size_t)NN * 512, Xt, Wt, P, 512, nullptr);
    }
    k_padd<<<NN * 128 / TPB, TPB>>>();

    // SAGE (gather, fused combine) -> B
    k_sage_gather<<<NN * 64 / TPB, TPB>>>(sage_bl);

    // GCN1: hw -> C, gather+bias+relu -> A
    {
        dim3 grid(256 / 64, NN / 64);
        sgemm64<<<grid, 256>>>(NN, 256, 256, B, 256, gcn1_W, 256, C, 256);
    }
    k_gcn_gather<<<NN * 64 / TPB, TPB>>>(C, gcn1_b, A, 6);

    // GCN2: hw -> D, gather+bias+relu -> E
    {
        dim3 grid(128 / 64, NN / 64);
        sgemm64<<<grid, 256>>>(NN, 128, 256, A, 256, gcn2_W, 128, D, 128);
    }
    k_gcn_gather<<<NN * 32 / TPB, TPB>>>(D, gcn2_b, E, 5);

    // fused fc1+fc2: E -> C
    k_fc12<<<NN / 64, 256>>>(E, fc1_W, fc1_b, fc2_W, fc2_b, C);

    // head GEMM (4096 x 16384 x 128): 4 k-tiles
    k_packAh<<<NN * 128 / 2 / TPB, TPB>>>(C, Ht, 128, 128);
    {
        dim3 grid(16384 / 128, NN / 128, 1);
        gemm_fp16p<<<grid, 256, GSMEM>>>(4, 4, 0, Ht, OWt, out, 16384, out_b);
    }
}